// round 12
// baseline (speedup 1.0000x reference)
#include <cuda_runtime.h>
#include <math.h>

#define Bb   16
#define Tt   512
#define Pdim 1024
#define Ddim 2048
#define G4   8192      // 4*D
#define LNEPS 1e-3f

#define NCTA 128       // persistent-scan grid (all co-resident; <= 148 SMs)
#define NTHR 256

// smem layout (float offsets) for scan kernel
#define SM_HST    0        // H transposed [1024][20] (pad) = 20480 floats (80KB)
#define SM_WT     20480    // weight tiles [3][32][64] = 6144 floats (24KB)
#define SM_GRED   26624    // phase A partials [8][16][64] = 8192 floats (32KB)
#define SM_HPART  26624    // phase B partials [16][16][8] = 2048 (union w/ Gred)
#define SM_PWS    34816    // persistent Pw slice [2048][8] = 16384 floats (64KB)
#define SM_FLOATS 51200
#define SM_BYTES  (SM_FLOATS * 4)   // 204800 B <= 227KB cap

// ---------------- scratch (static device globals; no allocation) -------------
__device__ float g_XG[(size_t)Bb * Tt * G4];        // 256 MB: pre-activations
__device__ float g_BUF[3][(size_t)Bb * Tt * Pdim];  // 3 x 32 MB ping-pong
__device__ float g_ST[Ddim * Bb];                   // s transposed [d][b]
__device__ float g_HT[Pdim * Bb];                   // h transposed [p][b]
__device__ float g_C[Bb * Ddim];                    // cell state

// grid barrier: monotonic counter
__device__ unsigned g_cnt;

__device__ __forceinline__ float sigm(float x) { return 1.0f / (1.0f + expf(-x)); }

// ---------------- packed f32x2 helpers (Blackwell) ---------------------------
__device__ __forceinline__ unsigned long long fma2(unsigned long long a,
                                                   unsigned long long b,
                                                   unsigned long long c) {
    unsigned long long d;
    asm("fma.rn.f32x2 %0, %1, %2, %3;" : "=l"(d) : "l"(a), "l"(b), "l"(c));
    return d;
}
__device__ __forceinline__ unsigned long long pack2(float lo, float hi) {
    unsigned long long r;
    asm("mov.b64 %0, {%1, %2};" : "=l"(r) : "f"(lo), "f"(hi));
    return r;
}
__device__ __forceinline__ float2 unpack2(unsigned long long v) {
    float2 r;
    asm("mov.b64 {%0, %1}, %2;" : "=f"(r.x), "=f"(r.y) : "l"(v));
    return r;
}

// ---------------- cp.async helpers -------------------------------------------
__device__ __forceinline__ void cpa16(unsigned dst, const void* src) {
    asm volatile("cp.async.cg.shared.global [%0], [%1], 16;"
                 :: "r"(dst), "l"(src));
}
__device__ __forceinline__ void cpa_commit() {
    asm volatile("cp.async.commit_group;" ::: "memory");
}
__device__ __forceinline__ void cpa_wait1() {
    asm volatile("cp.async.wait_group 1;" ::: "memory");
}
__device__ __forceinline__ void cpa_wait0() {
    asm volatile("cp.async.wait_group 0;" ::: "memory");
}

// ---------------- software grid barrier (monotonic, red.release) ------------
__device__ __forceinline__ void grid_sync(unsigned& target) {
    __syncthreads();
    target += NCTA;
    if (threadIdx.x == 0) {
        __threadfence();
        asm volatile("red.release.gpu.global.add.u32 [%0], 1;" :: "l"(&g_cnt));
        unsigned v;
        do {
            asm volatile("ld.acquire.gpu.global.u32 %0, [%1];" : "=r"(v) : "l"(&g_cnt));
        } while (v < target);
    }
    __syncthreads();
}

// ---------------- init / reset ----------------------------------------------
__global__ void k_init(const float* __restrict__ state) {
    int i = blockIdx.x * blockDim.x + threadIdx.x;
    if (i < Bb * Ddim) g_C[i] = state[i];
    if (i < Bb * Pdim) {
        int b = i / Pdim, p = i % Pdim;
        g_HT[p * Bb + b] = state[Bb * Ddim + b * Ddim + p];
    }
}
__global__ void k_rst() { g_cnt = 0; }

// ---------------- big GEMM: C[M,N] = A @ W + bias ---------------------------
// 128x128x16 tiles, double-buffered smem, one sync per k-tile, 2 CTAs/SM.
// convmode==1: row r of A starts at ((r/511)*512 + r%511)*1024, spans 2048.
__global__ void __launch_bounds__(NTHR, 2) k_gemm(const float* __restrict__ A,
                                                  const float* __restrict__ W,
                                                  const float* __restrict__ bias,
                                                  float* __restrict__ C,
                                                  int M, int N, int K, int convmode) {
    __shared__ float As[2][16][132];
    __shared__ float Bs[2][16][128];

    int tid = threadIdx.x;
    int tx = tid & 15, ty = tid >> 4;
    int m0 = blockIdx.y * 128, n0 = blockIdx.x * 128;

    int ar = tid >> 1, ac = (tid & 1) * 8;
    int br = tid >> 4, bc = (tid & 15) * 8;
    int r = m0 + ar;
    bool rok = (r < M);
    size_t abase = 0;
    if (rok) abase = convmode ? ((size_t)((r / 511) * 512 + (r % 511))) * (size_t)Pdim
                              : (size_t)r * (size_t)K;

    unsigned long long acc[8][4];
#pragma unroll
    for (int i = 0; i < 8; i++)
#pragma unroll
        for (int j = 0; j < 4; j++) acc[i][j] = 0ull;

    {
        float4 a0 = make_float4(0.f, 0.f, 0.f, 0.f), a1 = a0;
        if (rok) {
            a0 = *(const float4*)(A + abase + ac);
            a1 = *(const float4*)(A + abase + ac + 4);
        }
        float4 b0v = *(const float4*)(W + (size_t)br * N + n0 + bc);
        float4 b1v = *(const float4*)(W + (size_t)br * N + n0 + bc + 4);
#pragma unroll
        for (int j = 0; j < 4; j++) {
            As[0][ac + j][ar]     = (&a0.x)[j];
            As[0][ac + 4 + j][ar] = (&a1.x)[j];
        }
        *(float4*)&Bs[0][br][bc]     = b0v;
        *(float4*)&Bs[0][br][bc + 4] = b1v;
    }
    __syncthreads();

    int buf = 0;
    for (int k0 = 0; k0 < K; k0 += 16) {
        bool more = (k0 + 16) < K;
        float4 na0 = make_float4(0.f, 0.f, 0.f, 0.f), na1 = na0, nb0, nb1;
        if (more) {
            if (rok) {
                na0 = *(const float4*)(A + abase + k0 + 16 + ac);
                na1 = *(const float4*)(A + abase + k0 + 16 + ac + 4);
            }
            nb0 = *(const float4*)(W + (size_t)(k0 + 16 + br) * N + n0 + bc);
            nb1 = *(const float4*)(W + (size_t)(k0 + 16 + br) * N + n0 + bc + 4);
        }
#pragma unroll
        for (int kk = 0; kk < 16; kk++) {
            float4 av0 = *(const float4*)&As[buf][kk][ty * 8];
            float4 av1 = *(const float4*)&As[buf][kk][ty * 8 + 4];
            ulonglong2 bb0 = *(const ulonglong2*)&Bs[buf][kk][tx * 8];
            ulonglong2 bb1 = *(const ulonglong2*)&Bs[buf][kk][tx * 8 + 4];
            float aa[8] = {av0.x, av0.y, av0.z, av0.w, av1.x, av1.y, av1.z, av1.w};
#pragma unroll
            for (int i = 0; i < 8; i++) {
                unsigned long long ap = pack2(aa[i], aa[i]);
                acc[i][0] = fma2(ap, bb0.x, acc[i][0]);
                acc[i][1] = fma2(ap, bb0.y, acc[i][1]);
                acc[i][2] = fma2(ap, bb1.x, acc[i][2]);
                acc[i][3] = fma2(ap, bb1.y, acc[i][3]);
            }
        }
        if (more) {
            int nb = buf ^ 1;
#pragma unroll
            for (int j = 0; j < 4; j++) {
                As[nb][ac + j][ar]     = (&na0.x)[j];
                As[nb][ac + 4 + j][ar] = (&na1.x)[j];
            }
            *(float4*)&Bs[nb][br][bc]     = nb0;
            *(float4*)&Bs[nb][br][bc + 4] = nb1;
        }
        __syncthreads();
        buf ^= 1;
    }

#pragma unroll
    for (int i = 0; i < 8; i++) {
        int rr = m0 + ty * 8 + i;
        if (rr < M) {
            float* cp = C + (size_t)rr * (size_t)N + n0 + tx * 8;
            const float* bp = bias + n0 + tx * 8;
#pragma unroll
            for (int jj = 0; jj < 4; jj++) {
                float2 v = unpack2(acc[i][jj]);
                cp[jj * 2 + 0] = v.x + bp[jj * 2 + 0];
                cp[jj * 2 + 1] = v.y + bp[jj * 2 + 1];
            }
        }
    }
}

// ---------------- persistent scan: whole-layer LSTM recurrence ---------------
// 128 CTAs x 256 thr. CTA owns gate d-slice [cta*16, cta*16+16) (64 G-cols)
// and proj col-slice [cta*8, cta*8+8). Weights streamed via cp.async into
// CTA-shared 32k x 64col tiles; each lane holds all 16 batch rows in regs.
__global__ void __launch_bounds__(NTHR, 1) k_scan(const float* __restrict__ Wh,
                                                  const float* __restrict__ Pw,
                                                  const float* __restrict__ XG,
                                                  float* __restrict__ RAW,
                                                  int T) {
    extern __shared__ float sm[];
    float* Hst   = sm + SM_HST;    // [k][20]
    float* Wt    = sm + SM_WT;     // [3][32][64]
    float* Gred  = sm + SM_GRED;   // [8][16][64]
    float* Hpart = sm + SM_HPART;
    float* Pws   = sm + SM_PWS;    // [2048][8]

    unsigned smem_u32;
    {
        void* p = sm;
        smem_u32 = (unsigned)__cvta_generic_to_shared(p);
    }
    const unsigned wt_u32 = smem_u32 + SM_WT * 4;

    const int tid = threadIdx.x;
    const int cta = blockIdx.x;
    const int d0 = cta * 16;   // gate d-slice
    const int p0 = cta * 8;    // proj col-slice

    // phase A mapping: warp = 4 k per tile; lane = (ksub, cq)
    const int w    = tid >> 5;
    const int lane = tid & 31;
    const int ksub = lane >> 4;
    const int cq   = lane & 15;
    const int lc   = (cq >> 2) * 16 + (cq & 3) * 4;   // local col (0..63)

    // cp.async fill mapping (2 x 16B per thread per tile)
    // e = tid + i*256: row = e>>4 (0..31), q = e&15 -> local col q*4
    const int f_row0 = tid >> 4, f_q0 = tid & 15;

    // gate/cell mapping: one (b, dl) per thread
    const int gb = tid >> 4;
    const int dl = tid & 15;
    float c_reg = g_C[gb * Ddim + d0 + dl];

    // phase B mapping
    const int b2 = tid & 15;
    const int ks = tid >> 4;          // 16 k-splits of 128

    unsigned bar_target = 0;

    // ---- persistent Pw slice ----
    {
        const float* pwb = Pw + p0;
#pragma unroll 4
        for (int e = tid; e < 4096; e += NTHR) {
            int k = e >> 1, hf = (e & 1) * 4;
            *(float4*)&Pws[k * 8 + hf] =
                *(const float4*)(pwb + (size_t)k * Pdim + hf);
        }
    }
    __syncthreads();

    for (int t = 0; t < T; t++) {
        // ---- issue weight tiles 0,1 via cp.async ----
#pragma unroll
        for (int pt = 0; pt < 2; pt++) {
#pragma unroll
            for (int i = 0; i < 2; i++) {
                int row = f_row0 + i * 16;
                unsigned dst = wt_u32 + (unsigned)((pt * 2048 + row * 64 + f_q0 * 4) * 4);
                const float* src = Wh + (size_t)(pt * 32 + row) * G4
                                 + (f_q0 >> 2) * Ddim + d0 + (f_q0 & 3) * 4;
                cpa16(dst, src);
            }
            cpa_commit();
        }

        // ---- prefetch XG gates for this step ----
        float xgv[4];
        {
            const float* xgp = XG + ((size_t)gb * T + t) * (size_t)G4 + d0 + dl;
#pragma unroll
            for (int g = 0; g < 4; g++) xgv[g] = xgp[(size_t)g * Ddim];
        }

        // ---- stage H (transposed) into smem ----
#pragma unroll 4
        for (int i = 0; i < 16; i++) {
            int idx = tid + i * NTHR;          // 0..4095
            int p = idx >> 2, q4 = (idx & 3) * 4;
            float4 v = *(const float4*)(g_HT + p * Bb + q4);
            *(float4*)&Hst[p * 20 + q4] = v;
        }
        __syncthreads();

        // ---- phase A: G partials over 32 weight tiles ----
        unsigned long long acc[16][2];
#pragma unroll
        for (int b = 0; b < 16; b++) { acc[b][0] = 0ull; acc[b][1] = 0ull; }

        int buf = 0;
        for (int kt = 0; kt < 32; kt++) {
            if (kt == 31) cpa_wait0(); else cpa_wait1();
            __syncthreads();
            // issue tile kt+2
            if (kt + 2 < 32) {
                int nb = (kt + 2) % 3;
#pragma unroll
                for (int i = 0; i < 2; i++) {
                    int row = f_row0 + i * 16;
                    unsigned dst = wt_u32 + (unsigned)((nb * 2048 + row * 64 + f_q0 * 4) * 4);
                    const float* src = Wh + (size_t)((kt + 2) * 32 + row) * G4
                                     + (f_q0 >> 2) * Ddim + d0 + (f_q0 & 3) * 4;
                    cpa16(dst, src);
                }
                cpa_commit();
            }
            // compute: this warp's 4 k rows of the tile; lane handles 2 k
            const float* wtb = Wt + buf * 2048;
#pragma unroll
            for (int tt = 0; tt < 2; tt++) {
                int kk = w * 4 + ksub * 2 + tt;          // k within tile
                int kg = kt * 32 + kk;                   // global k
                ulonglong2 wv = *(const ulonglong2*)&wtb[kk * 64 + lc];
                float4 h0 = *(const float4*)&Hst[kg * 20 + 0];
                float4 h1 = *(const float4*)&Hst[kg * 20 + 4];
                float4 h2 = *(const float4*)&Hst[kg * 20 + 8];
                float4 h3 = *(const float4*)&Hst[kg * 20 + 12];
                float hh[16] = {h0.x, h0.y, h0.z, h0.w, h1.x, h1.y, h1.z, h1.w,
                                h2.x, h2.y, h2.z, h2.w, h3.x, h3.y, h3.z, h3.w};
#pragma unroll
                for (int b = 0; b < 16; b++) {
                    unsigned long long ap = pack2(hh[b], hh[b]);
                    acc[b][0] = fma2(ap, wv.x, acc[b][0]);
                    acc[b][1] = fma2(ap, wv.y, acc[b][1]);
                }
            }
            buf = (buf + 1) % 3;
        }

        // ---- ksub reduction (bfly 16) + store warp partials ----
#pragma unroll
        for (int b = 0; b < 16; b++) {
            float2 v0 = unpack2(acc[b][0]);
            float2 v1 = unpack2(acc[b][1]);
            v0.x += __shfl_xor_sync(0xFFFFFFFFu, v0.x, 16);
            v0.y += __shfl_xor_sync(0xFFFFFFFFu, v0.y, 16);
            v1.x += __shfl_xor_sync(0xFFFFFFFFu, v1.x, 16);
            v1.y += __shfl_xor_sync(0xFFFFFFFFu, v1.y, 16);
            if (ksub == 0)
                *(float4*)&Gred[w * 1024 + b * 64 + lc] =
                    make_float4(v0.x, v0.y, v1.x, v1.y);
        }
        __syncthreads();

        // ---- gates + cell update ----
        {
            float gv[4];
#pragma unroll
            for (int g = 0; g < 4; g++) {
                float s = 0.0f;
#pragma unroll
                for (int wf = 0; wf < 8; wf++)
                    s += Gred[wf * 1024 + gb * 64 + g * 16 + dl];
                gv[g] = s + xgv[g];
            }
            float cc = sigm(gv[2] + 1.0f) * c_reg + sigm(gv[0]) * tanhf(gv[1]);
            c_reg = cc;
            float sv = sigm(gv[3]) * tanhf(cc);
            g_ST[(size_t)(d0 + dl) * Bb + gb] = sv;
        }

        grid_sync(bar_target);

        // ---- phase B: H = S @ proj for this CTA's 8 output cols ----
        {
            unsigned long long acc2[4] = {0ull, 0ull, 0ull, 0ull};
            const float* sg = g_ST + (size_t)(ks * 128) * Bb + b2;
            const float* pwk = Pws + ks * 128 * 8;
            float sa0 = sg[0], sa1 = sg[16], sa2 = sg[32], sa3 = sg[48];
            float sb0 = sg[64], sb1 = sg[80], sb2 = sg[96], sb3 = sg[112];
#pragma unroll 1
            for (int k = 0; k < 128; k += 4) {
                float n0v, n1v, n2v, n3v;
                bool more = k < 120;
                if (more) {
                    const float* sq = sg + (size_t)(k + 8) * 16;
                    n0v = sq[0]; n1v = sq[16]; n2v = sq[32]; n3v = sq[48];
                }
#pragma unroll
                for (int u = 0; u < 4; u++) {
                    float s = (u == 0) ? sa0 : (u == 1) ? sa1 : (u == 2) ? sa2 : sa3;
                    unsigned long long sp = pack2(s, s);
                    ulonglong2 w0 = *(const ulonglong2*)(pwk + (k + u) * 8);
                    ulonglong2 w1 = *(const ulonglong2*)(pwk + (k + u) * 8 + 4);
                    acc2[0] = fma2(sp, w0.x, acc2[0]);
                    acc2[1] = fma2(sp, w0.y, acc2[1]);
                    acc2[2] = fma2(sp, w1.x, acc2[2]);
                    acc2[3] = fma2(sp, w1.y, acc2[3]);
                }
                sa0 = sb0; sa1 = sb1; sa2 = sb2; sa3 = sb3;
                sb0 = n0v; sb1 = n1v; sb2 = n2v; sb3 = n3v;
            }
            float* hp = Hpart + (ks * 16 + b2) * 8;
#pragma unroll
            for (int jj = 0; jj < 4; jj++) {
                float2 v = unpack2(acc2[jj]);
                hp[jj * 2 + 0] = v.x;
                hp[jj * 2 + 1] = v.y;
            }
        }
        __syncthreads();
        if (tid < 128) {
            int b = tid >> 3, col = tid & 7;
            float h = 0.0f;
#pragma unroll
            for (int k2 = 0; k2 < 16; k2++)
                h += Hpart[(k2 * 16 + b) * 8 + col];
            g_HT[(p0 + col) * Bb + b] = h;
            RAW[((size_t)b * T + t) * (size_t)Pdim + p0 + col] = h;
        }

        grid_sync(bar_target);
    }

    // write back final cell state
    g_C[gb * Ddim + d0 + dl] = c_reg;
}

// ---------------- layernorm over last dim (1024) ----------------------------
__global__ void k_ln(const float* __restrict__ X, float* __restrict__ Y,
                     const float* __restrict__ gamma, const float* __restrict__ beta) {
    __shared__ float red[256];
    int row = blockIdx.x;
    const float* x = X + (size_t)row * Pdim;
    float* y = Y + (size_t)row * Pdim;
    int tid = threadIdx.x;

    float s = 0.0f;
    for (int i = tid; i < Pdim; i += 256) s += x[i];
    red[tid] = s; __syncthreads();
    for (int o = 128; o > 0; o >>= 1) {
        if (tid < o) red[tid] += red[tid + o];
        __syncthreads();
    }
    float mean = red[0] * (1.0f / Pdim);
    __syncthreads();

    float v = 0.0f;
    for (int i = tid; i < Pdim; i += 256) { float d = x[i] - mean; v += d * d; }
    red[tid] = v; __syncthreads();
    for (int o = 128; o > 0; o >>= 1) {
        if (tid < o) red[tid] += red[tid + o];
        __syncthreads();
    }
    float rstd = rsqrtf(red[0] * (1.0f / Pdim) + LNEPS);
    __syncthreads();

    for (int i = tid; i < Pdim; i += 256)
        y[i] = (x[i] - mean) * rstd * gamma[i] + beta[i];
}

// ---------------- final c,h copy --------------------------------------------
__global__ void k_out_ch(float* __restrict__ oc, float* __restrict__ oh) {
    int idx = blockIdx.x * blockDim.x + threadIdx.x;
    if (idx < Bb * Ddim) oc[idx] = g_C[idx];
    if (idx < Bb * Pdim) {
        int b = idx / Pdim, p = idx % Pdim;
        oh[idx] = g_HT[p * Bb + b];
    }
}

// ---------------- host driver -----------------------------------------------
extern "C" void kernel_launch(void* const* d_in, const int* in_sizes, int n_in,
                              void* d_out, int out_size) {
    const float* inputs  = (const float*)d_in[0];
    const float* state   = (const float*)d_in[1];
    const float* kernels = (const float*)d_in[2];
    const float* biases  = (const float*)d_in[3];
    const float* projs   = (const float*)d_in[4];
    const float* gamma   = (const float*)d_in[5];
    const float* beta    = (const float*)d_in[6];
    const float* convw   = (const float*)d_in[7];
    const float* convb   = (const float*)d_in[8];
    float* out = (float*)d_out;

    cudaFuncSetAttribute(k_scan, cudaFuncAttributeMaxDynamicSharedMemorySize,
                         SM_BYTES);

    float* BUF = nullptr;
    float* XG  = nullptr;
    cudaGetSymbolAddress((void**)&BUF, g_BUF);
    cudaGetSymbolAddress((void**)&XG, g_XG);
    const size_t BUFSZ = (size_t)Bb * Tt * Pdim;
    float* A  = BUF;
    float* Bu = BUF + BUFSZ;
    float* Cu = BUF + 2 * BUFSZ;

    k_init<<<(Bb * Ddim + 255) / 256, 256>>>(state);

    const float* cur = inputs;
    for (int l = 0; l < 4; l++) {
        int T = (l < 2) ? 512 : 511;
        int Mrows = Bb * T;
        const float* Wx = kernels + (size_t)l * 2 * Pdim * G4;
        const float* Wh = Wx + (size_t)Pdim * G4;
        const float* bi = biases + l * G4;
        const float* Pw = projs + (size_t)l * Ddim * Pdim;

        // pre-activations XG = cur @ Wx + bias
        dim3 gx(G4 / 128, (Mrows + 127) / 128);
        k_gemm<<<gx, NTHR>>>(cur, Wx, bi, XG, Mrows, G4, Pdim, 0);

        // whole-layer recurrence in ONE persistent launch
        k_rst<<<1, 1>>>();
        k_scan<<<NCTA, NTHR, SM_BYTES>>>(Wh, Pw, XG, A, T);

        // layernorm
        float* LNout;
        if (l == 0)      LNout = Bu;
        else if (l == 1) LNout = Cu;
        else if (l == 2) LNout = Cu;
        else             LNout = out;
        k_ln<<<Mrows, 256>>>(A, LNout, gamma, beta);

        if (l == 1) {
            // temporal conv (window 2, VALID): GEMM with overlapped A rows
            int Mc = Bb * 511;
            dim3 gc(Pdim / 128, (Mc + 127) / 128);
            k_gemm<<<gc, NTHR>>>(Cu, convw, convb, Bu, Mc, Pdim, 2 * Pdim, 1);
            cur = Bu;
        } else if (l == 0) {
            cur = Bu;
        } else if (l == 2) {
            cur = Cu;
        }
    }

    // outputs: out [16,511,1024], then c [16,2048], then h [16,1024]
    size_t off_c = (size_t)Bb * 511 * Pdim;
    size_t off_h = off_c + (size_t)Bb * Ddim;
    k_out_ch<<<(Bb * Ddim + 255) / 256, 256>>>(out + off_c, out + off_h);
}

// round 14
// speedup vs baseline: 1.1124x; 1.1124x over previous
#include <cuda_runtime.h>
#include <cuda_bf16.h>
#include <math.h>

#define Bb   16
#define Tt   512
#define Pdim 1024
#define Ddim 2048
#define G4   8192      // 4*D
#define LNEPS 1e-3f

#define NCTA 128       // persistent-scan grid (all co-resident; <= 148 SMs)
#define NTHR 256

// smem layout (float offsets) for scan kernel
#define SM_HST    0        // H transposed [1024][20] (pad) = 20480 floats (80KB)
#define SM_WT     20480    // weight tiles [3][32][64] = 6144 floats (24KB)
#define SM_GRED   26624    // phase A partials [8][16][64] = 8192 floats (32KB)
#define SM_HPART  26624    // phase B partials [16][16][8] = 2048 (union w/ Gred)
#define SM_PWS    34816    // persistent Pw slice [2048][8] = 16384 floats (64KB)
#define SM_FLOATS 51200
#define SM_BYTES  (SM_FLOATS * 4)

// tensor-GEMM smem (bytes per buffer)
#define SA_H 0          // A hi: [128][40 bf16] = 10240 B (80 B rows, ldmatrix-safe)
#define SA_M 10240      // A lo
#define SB_H 20480      // B hi: [32][136 bf16] = 8704 B (272 B rows)
#define SB_M 29184      // B lo
#define BUFB 37888
#define SMEM_TC (2 * BUFB)   // 75776 B

// ---------------- scratch (static device globals; no allocation) -------------
__device__ float g_XG[(size_t)Bb * Tt * G4];        // 256 MB: pre-activations
__device__ float g_BUF[3][(size_t)Bb * Tt * Pdim];  // 3 x 32 MB ping-pong
__device__ float g_ST[Ddim * Bb];                   // s transposed [d][b]
__device__ float g_HT[Pdim * Bb];                   // h transposed [p][b]
__device__ float g_C[Bb * Ddim];                    // cell state

// bf16 split buffers for tensor GEMM
__device__ __nv_bfloat16 g_Ah[(size_t)Bb * Tt * Pdim];
__device__ __nv_bfloat16 g_Am[(size_t)Bb * Tt * Pdim];
__device__ __nv_bfloat16 g_Wh[(size_t)Pdim * G4];   // covers conv W (2048x1024) too
__device__ __nv_bfloat16 g_Wm[(size_t)Pdim * G4];

// grid barrier: monotonic counter
__device__ unsigned g_cnt;

__device__ __forceinline__ float sigm(float x) { return 1.0f / (1.0f + expf(-x)); }

// ---------------- packed f32x2 helpers ---------------------------------------
__device__ __forceinline__ unsigned long long fma2(unsigned long long a,
                                                   unsigned long long b,
                                                   unsigned long long c) {
    unsigned long long d;
    asm("fma.rn.f32x2 %0, %1, %2, %3;" : "=l"(d) : "l"(a), "l"(b), "l"(c));
    return d;
}
__device__ __forceinline__ unsigned long long pack2(float lo, float hi) {
    unsigned long long r;
    asm("mov.b64 %0, {%1, %2};" : "=l"(r) : "f"(lo), "f"(hi));
    return r;
}
__device__ __forceinline__ float2 unpack2(unsigned long long v) {
    float2 r;
    asm("mov.b64 {%0, %1}, %2;" : "=f"(r.x), "=f"(r.y) : "l"(v));
    return r;
}

// ---------------- mma / ldmatrix / cp.async helpers --------------------------
__device__ __forceinline__ void ldsm_x4(unsigned* r, unsigned addr) {
    asm volatile("ldmatrix.sync.aligned.m8n8.x4.shared.b16 {%0,%1,%2,%3}, [%4];"
                 : "=r"(r[0]), "=r"(r[1]), "=r"(r[2]), "=r"(r[3]) : "r"(addr));
}
__device__ __forceinline__ void ldsm_x2t(unsigned* r, unsigned addr) {
    asm volatile("ldmatrix.sync.aligned.m8n8.x2.trans.shared.b16 {%0,%1}, [%2];"
                 : "=r"(r[0]), "=r"(r[1]) : "r"(addr));
}
__device__ __forceinline__ void mma_bf16(float* c, const unsigned* a, const unsigned* b) {
    asm volatile("mma.sync.aligned.m16n8k16.row.col.f32.bf16.bf16.f32 "
                 "{%0,%1,%2,%3}, {%4,%5,%6,%7}, {%8,%9}, {%0,%1,%2,%3};"
                 : "+f"(c[0]), "+f"(c[1]), "+f"(c[2]), "+f"(c[3])
                 : "r"(a[0]), "r"(a[1]), "r"(a[2]), "r"(a[3]),
                   "r"(b[0]), "r"(b[1]));
}
__device__ __forceinline__ void cpa16z(unsigned dst, const void* src, int sz) {
    asm volatile("cp.async.cg.shared.global [%0], [%1], 16, %2;"
                 :: "r"(dst), "l"(src), "r"(sz));
}
__device__ __forceinline__ void cpa16(unsigned dst, const void* src) {
    asm volatile("cp.async.cg.shared.global [%0], [%1], 16;"
                 :: "r"(dst), "l"(src));
}
__device__ __forceinline__ void cpa_commit() {
    asm volatile("cp.async.commit_group;" ::: "memory");
}
__device__ __forceinline__ void cpa_wait1() {
    asm volatile("cp.async.wait_group 1;" ::: "memory");
}
__device__ __forceinline__ void cpa_wait0() {
    asm volatile("cp.async.wait_group 0;" ::: "memory");
}

// ---------------- software grid barrier (monotonic, red.release) ------------
__device__ __forceinline__ void grid_sync(unsigned& target) {
    __syncthreads();
    target += NCTA;
    if (threadIdx.x == 0) {
        __threadfence();
        asm volatile("red.release.gpu.global.add.u32 [%0], 1;" :: "l"(&g_cnt));
        unsigned v;
        do {
            asm volatile("ld.acquire.gpu.global.u32 %0, [%1];" : "=r"(v) : "l"(&g_cnt));
        } while (v < target);
    }
    __syncthreads();
}

// ---------------- init / reset ----------------------------------------------
__global__ void k_init(const float* __restrict__ state) {
    int i = blockIdx.x * blockDim.x + threadIdx.x;
    if (i < Bb * Ddim) g_C[i] = state[i];
    if (i < Bb * Pdim) {
        int b = i / Pdim, p = i % Pdim;
        g_HT[p * Bb + b] = state[Bb * Ddim + b * Ddim + p];
    }
}
__global__ void k_rst() { g_cnt = 0; }

// ---------------- fp32 -> bf16 (hi, lo) split conversion ---------------------
__global__ void k_cvt(const float* __restrict__ src, __nv_bfloat16* __restrict__ h,
                      __nv_bfloat16* __restrict__ m, int n4) {
    int i = blockIdx.x * blockDim.x + threadIdx.x;
    if (i < n4) {
        float4 v = ((const float4*)src)[i];
        float vv[4] = {v.x, v.y, v.z, v.w};
        __nv_bfloat16 hv[4], mv[4];
#pragma unroll
        for (int j = 0; j < 4; j++) {
            hv[j] = __float2bfloat16_rn(vv[j]);
            mv[j] = __float2bfloat16_rn(vv[j] - __bfloat162float(hv[j]));
        }
        *(uint2*)&h[(size_t)i * 4] = *(uint2*)hv;
        *(uint2*)&m[(size_t)i * 4] = *(uint2*)mv;
    }
}

// ---------------- tensor-core split GEMM: C = A @ W + bias -------------------
// A logical [M][K] bf16 (h,m), convmode==1 -> row r base = ((r/511)*512+r%511)*1024
// W [K][N] bf16 (h,m). 128x128x32 tiles, 8 warps as 2m x 4n, m16n8k16 mma,
// D = AhBh + AhBm + AmBh (AmBm dropped, ~2^-18 rel).
__global__ void __launch_bounds__(256) k_gemm_tc(
    const __nv_bfloat16* __restrict__ Ah, const __nv_bfloat16* __restrict__ Am,
    const __nv_bfloat16* __restrict__ Wh, const __nv_bfloat16* __restrict__ Wm,
    const float* __restrict__ bias, float* __restrict__ C,
    int M, int N, int K, int convmode)
{
    extern __shared__ char gsm[];
    const unsigned sbase0 = (unsigned)__cvta_generic_to_shared(gsm);

    const int tid = threadIdx.x;
    const int l = tid & 31;
    const int wid = tid >> 5;
    const int wm = wid >> 2, wn = wid & 3;    // 2 x 4 warp grid
    const int m0 = blockIdx.y * 128, n0 = blockIdx.x * 128;
    const int nk = K / 32;

    float c[4][4][4];
#pragma unroll
    for (int a = 0; a < 4; a++)
#pragma unroll
        for (int b = 0; b < 4; b++)
#pragma unroll
            for (int d = 0; d < 4; d++) c[a][b][d] = 0.0f;

    // ---- staging: 8 x cp.async 16B per thread per chunk ----
    auto stage = [&](int kt, int buf) {
        const unsigned sb = sbase0 + (unsigned)(buf * BUFB);
        const int k0 = kt * 32;
#pragma unroll
        for (int i = 0; i < 2; i++) {
            int u = tid * 2 + i;
            // A: 128 rows x 32 k; row = u>>2, 16B unit = u&3 (8 bf16)
            int ar = u >> 2, au = u & 3;
            int r = m0 + ar;
            int ok = (r < M) ? 16 : 0;
            size_t abase = 0;
            if (ok) abase = convmode ? ((size_t)((r / 511) * 512 + (r % 511))) * 1024
                                     : (size_t)r * (size_t)K;
            unsigned da = sb + SA_H + (unsigned)(ar * 80 + au * 16);
            cpa16z(da, Ah + abase + k0 + au * 8, ok);
            cpa16z(da + (SA_M - SA_H), Am + abase + k0 + au * 8, ok);
            // B: 32 k-rows x 128 n; row = u>>4, unit = u&15
            int br = u >> 4, bu = u & 15;
            unsigned db = sb + SB_H + (unsigned)(br * 272 + bu * 16);
            const size_t wof = (size_t)(k0 + br) * (size_t)N + n0 + bu * 8;
            cpa16(db, Wh + wof);
            cpa16(db + (SB_M - SB_H), Wm + wof);
        }
    };

    stage(0, 0);
    cpa_commit();

    const int arow = (l & 7) + ((l & 8) ? 8 : 0);
    const int aoff_hi = (l & 16) ? 16 : 0;
    const int brow_base = (l & 7) + ((l & 8) ? 8 : 0);

    for (int kt = 0; kt < nk; kt++) {
        if (kt + 1 < nk) {
            stage(kt + 1, (kt + 1) & 1);
            cpa_commit();
            cpa_wait1();
        } else {
            cpa_wait0();
        }
        __syncthreads();

        const unsigned sb = sbase0 + (unsigned)((kt & 1) * BUFB);
#pragma unroll
        for (int ks = 0; ks < 2; ks++) {
            // B fragments (all 4 n-tiles, hi+lo)
            unsigned bh[4][2], bm[4][2];
            int brow = ks * 16 + brow_base;
#pragma unroll
            for (int nt = 0; nt < 4; nt++) {
                unsigned ab = sb + SB_H + (unsigned)(brow * 272 + (wn * 32 + nt * 8) * 2);
                ldsm_x2t(bh[nt], ab);
                ldsm_x2t(bm[nt], ab + (SB_M - SB_H));
            }
#pragma unroll
            for (int mt = 0; mt < 4; mt++) {
                unsigned ah4[4], am4[4];
                unsigned aa = sb + SA_H +
                    (unsigned)((wm * 64 + mt * 16 + arow) * 80 + ks * 32 + aoff_hi);
                ldsm_x4(ah4, aa);
                ldsm_x4(am4, aa + (SA_M - SA_H));
#pragma unroll
                for (int nt = 0; nt < 4; nt++) {
                    mma_bf16(c[mt][nt], ah4, bh[nt]);
                    mma_bf16(c[mt][nt], ah4, bm[nt]);
                    mma_bf16(c[mt][nt], am4, bh[nt]);
                }
            }
        }
        __syncthreads();
    }

    // ---- epilogue: + bias, write fp32 ----
#pragma unroll
    for (int mt = 0; mt < 4; mt++) {
        int r0 = m0 + wm * 64 + mt * 16 + (l >> 2);
#pragma unroll
        for (int nt = 0; nt < 4; nt++) {
            int col = n0 + wn * 32 + nt * 8 + (l & 3) * 2;
            float b0 = bias[col], b1 = bias[col + 1];
            if (r0 < M)
                *(float2*)&C[(size_t)r0 * N + col] =
                    make_float2(c[mt][nt][0] + b0, c[mt][nt][1] + b1);
            if (r0 + 8 < M)
                *(float2*)&C[(size_t)(r0 + 8) * N + col] =
                    make_float2(c[mt][nt][2] + b0, c[mt][nt][3] + b1);
        }
    }
}

// ---------------- persistent scan: whole-layer LSTM recurrence ---------------
__global__ void __launch_bounds__(NTHR, 1) k_scan(const float* __restrict__ Wh,
                                                  const float* __restrict__ Pw,
                                                  const float* __restrict__ XG,
                                                  float* __restrict__ RAW,
                                                  int T) {
    extern __shared__ float sm[];
    float* Hst   = sm + SM_HST;    // [k][20]
    float* Wt    = sm + SM_WT;     // [3][32][64]
    float* Gred  = sm + SM_GRED;   // [8][16][64]
    float* Hpart = sm + SM_HPART;
    float* Pws   = sm + SM_PWS;    // [2048][8]

    unsigned smem_u32;
    {
        void* p = sm;
        smem_u32 = (unsigned)__cvta_generic_to_shared(p);
    }
    const unsigned wt_u32 = smem_u32 + SM_WT * 4;

    const int tid = threadIdx.x;
    const int cta = blockIdx.x;
    const int d0 = cta * 16;   // gate d-slice
    const int p0 = cta * 8;    // proj col-slice

    const int w    = tid >> 5;
    const int lane = tid & 31;
    const int ksub = lane >> 4;
    const int cq   = lane & 15;
    const int lc   = (cq >> 2) * 16 + (cq & 3) * 4;   // local col (0..63)

    const int f_row0 = tid >> 4, f_q0 = tid & 15;

    const int gb = tid >> 4;
    const int dl = tid & 15;
    float c_reg = g_C[gb * Ddim + d0 + dl];

    const int b2 = tid & 15;
    const int ks = tid >> 4;          // 16 k-splits of 128

    unsigned bar_target = 0;

    {
        const float* pwb = Pw + p0;
#pragma unroll 4
        for (int e = tid; e < 4096; e += NTHR) {
            int k = e >> 1, hf = (e & 1) * 4;
            *(float4*)&Pws[k * 8 + hf] =
                *(const float4*)(pwb + (size_t)k * Pdim + hf);
        }
    }
    __syncthreads();

    for (int t = 0; t < T; t++) {
#pragma unroll
        for (int pt = 0; pt < 2; pt++) {
#pragma unroll
            for (int i = 0; i < 2; i++) {
                int row = f_row0 + i * 16;
                unsigned dst = wt_u32 + (unsigned)((pt * 2048 + row * 64 + f_q0 * 4) * 4);
                const float* src = Wh + (size_t)(pt * 32 + row) * G4
                                 + (f_q0 >> 2) * Ddim + d0 + (f_q0 & 3) * 4;
                cpa16(dst, src);
            }
            cpa_commit();
        }

        float xgv[4];
        {
            const float* xgp = XG + ((size_t)gb * T + t) * (size_t)G4 + d0 + dl;
#pragma unroll
            for (int g = 0; g < 4; g++) xgv[g] = xgp[(size_t)g * Ddim];
        }

#pragma unroll 4
        for (int i = 0; i < 16; i++) {
            int idx = tid + i * NTHR;
            int p = idx >> 2, q4 = (idx & 3) * 4;
            float4 v = *(const float4*)(g_HT + p * Bb + q4);
            *(float4*)&Hst[p * 20 + q4] = v;
        }
        __syncthreads();

        unsigned long long acc[16][2];
#pragma unroll
        for (int b = 0; b < 16; b++) { acc[b][0] = 0ull; acc[b][1] = 0ull; }

        int buf = 0;
        for (int kt = 0; kt < 32; kt++) {
            if (kt == 31) cpa_wait0(); else cpa_wait1();
            __syncthreads();
            if (kt + 2 < 32) {
                int nb = (kt + 2) % 3;
#pragma unroll
                for (int i = 0; i < 2; i++) {
                    int row = f_row0 + i * 16;
                    unsigned dst = wt_u32 + (unsigned)((nb * 2048 + row * 64 + f_q0 * 4) * 4);
                    const float* src = Wh + (size_t)((kt + 2) * 32 + row) * G4
                                     + (f_q0 >> 2) * Ddim + d0 + (f_q0 & 3) * 4;
                    cpa16(dst, src);
                }
                cpa_commit();
            }
            const float* wtb = Wt + buf * 2048;
#pragma unroll
            for (int tt = 0; tt < 2; tt++) {
                int kk = w * 4 + ksub * 2 + tt;
                int kg = kt * 32 + kk;
                ulonglong2 wv = *(const ulonglong2*)&wtb[kk * 64 + lc];
                float4 h0 = *(const float4*)&Hst[kg * 20 + 0];
                float4 h1 = *(const float4*)&Hst[kg * 20 + 4];
                float4 h2 = *(const float4*)&Hst[kg * 20 + 8];
                float4 h3 = *(const float4*)&Hst[kg * 20 + 12];
                float hh[16] = {h0.x, h0.y, h0.z, h0.w, h1.x, h1.y, h1.z, h1.w,
                                h2.x, h2.y, h2.z, h2.w, h3.x, h3.y, h3.z, h3.w};
#pragma unroll
                for (int b = 0; b < 16; b++) {
                    unsigned long long ap = pack2(hh[b], hh[b]);
                    acc[b][0] = fma2(ap, wv.x, acc[b][0]);
                    acc[b][1] = fma2(ap, wv.y, acc[b][1]);
                }
            }
            buf = (buf + 1) % 3;
        }

#pragma unroll
        for (int b = 0; b < 16; b++) {
            float2 v0 = unpack2(acc[b][0]);
            float2 v1 = unpack2(acc[b][1]);
            v0.x += __shfl_xor_sync(0xFFFFFFFFu, v0.x, 16);
            v0.y += __shfl_xor_sync(0xFFFFFFFFu, v0.y, 16);
            v1.x += __shfl_xor_sync(0xFFFFFFFFu, v1.x, 16);
            v1.y += __shfl_xor_sync(0xFFFFFFFFu, v1.y, 16);
            if (ksub == 0)
                *(float4*)&Gred[w * 1024 + b * 64 + lc] =
                    make_float4(v0.x, v0.y, v1.x, v1.y);
        }
        __syncthreads();

        {
            float gv[4];
#pragma unroll
            for (int g = 0; g < 4; g++) {
                float s = 0.0f;
#pragma unroll
                for (int wf = 0; wf < 8; wf++)
                    s += Gred[wf * 1024 + gb * 64 + g * 16 + dl];
                gv[g] = s + xgv[g];
            }
            float cc = sigm(gv[2] + 1.0f) * c_reg + sigm(gv[0]) * tanhf(gv[1]);
            c_reg = cc;
            float sv = sigm(gv[3]) * tanhf(cc);
            g_ST[(size_t)(d0 + dl) * Bb + gb] = sv;
        }

        grid_sync(bar_target);

        {
            unsigned long long acc2[4] = {0ull, 0ull, 0ull, 0ull};
            const float* sg = g_ST + (size_t)(ks * 128) * Bb + b2;
            const float* pwk = Pws + ks * 128 * 8;
            float sa0 = sg[0], sa1 = sg[16], sa2 = sg[32], sa3 = sg[48];
            float sb0 = sg[64], sb1 = sg[80], sb2 = sg[96], sb3 = sg[112];
#pragma unroll 1
            for (int k = 0; k < 128; k += 4) {
                float n0v, n1v, n2v, n3v;
                bool more = k < 120;
                if (more) {
                    const float* sq = sg + (size_t)(k + 8) * 16;
                    n0v = sq[0]; n1v = sq[16]; n2v = sq[32]; n3v = sq[48];
                }
#pragma unroll
                for (int u = 0; u < 4; u++) {
                    float s = (u == 0) ? sa0 : (u == 1) ? sa1 : (u == 2) ? sa2 : sa3;
                    unsigned long long sp = pack2(s, s);
                    ulonglong2 w0 = *(const ulonglong2*)(pwk + (k + u) * 8);
                    ulonglong2 w1 = *(const ulonglong2*)(pwk + (k + u) * 8 + 4);
                    acc2[0] = fma2(sp, w0.x, acc2[0]);
                    acc2[1] = fma2(sp, w0.y, acc2[1]);
                    acc2[2] = fma2(sp, w1.x, acc2[2]);
                    acc2[3] = fma2(sp, w1.y, acc2[3]);
                }
                sa0 = sb0; sa1 = sb1; sa2 = sb2; sa3 = sb3;
                sb0 = n0v; sb1 = n1v; sb2 = n2v; sb3 = n3v;
            }
            float* hp = Hpart + (ks * 16 + b2) * 8;
#pragma unroll
            for (int jj = 0; jj < 4; jj++) {
                float2 v = unpack2(acc2[jj]);
                hp[jj * 2 + 0] = v.x;
                hp[jj * 2 + 1] = v.y;
            }
        }
        __syncthreads();
        if (tid < 128) {
            int b = tid >> 3, col = tid & 7;
            float h = 0.0f;
#pragma unroll
            for (int k2 = 0; k2 < 16; k2++)
                h += Hpart[(k2 * 16 + b) * 8 + col];
            g_HT[(p0 + col) * Bb + b] = h;
            RAW[((size_t)b * T + t) * (size_t)Pdim + p0 + col] = h;
        }

        grid_sync(bar_target);
    }

    g_C[gb * Ddim + d0 + dl] = c_reg;
}

// ---------------- layernorm over last dim (1024) ----------------------------
__global__ void k_ln(const float* __restrict__ X, float* __restrict__ Y,
                     const float* __restrict__ gamma, const float* __restrict__ beta) {
    __shared__ float red[256];
    int row = blockIdx.x;
    const float* x = X + (size_t)row * Pdim;
    float* y = Y + (size_t)row * Pdim;
    int tid = threadIdx.x;

    float s = 0.0f;
    for (int i = tid; i < Pdim; i += 256) s += x[i];
    red[tid] = s; __syncthreads();
    for (int o = 128; o > 0; o >>= 1) {
        if (tid < o) red[tid] += red[tid + o];
        __syncthreads();
    }
    float mean = red[0] * (1.0f / Pdim);
    __syncthreads();

    float v = 0.0f;
    for (int i = tid; i < Pdim; i += 256) { float d = x[i] - mean; v += d * d; }
    red[tid] = v; __syncthreads();
    for (int o = 128; o > 0; o >>= 1) {
        if (tid < o) red[tid] += red[tid + o];
        __syncthreads();
    }
    float rstd = rsqrtf(red[0] * (1.0f / Pdim) + LNEPS);
    __syncthreads();

    for (int i = tid; i < Pdim; i += 256)
        y[i] = (x[i] - mean) * rstd * gamma[i] + beta[i];
}

// ---------------- final c,h copy --------------------------------------------
__global__ void k_out_ch(float* __restrict__ oc, float* __restrict__ oh) {
    int idx = blockIdx.x * blockDim.x + threadIdx.x;
    if (idx < Bb * Ddim) oc[idx] = g_C[idx];
    if (idx < Bb * Pdim) {
        int b = idx / Pdim, p = idx % Pdim;
        oh[idx] = g_HT[p * Bb + b];
    }
}

// ---------------- host driver -----------------------------------------------
extern "C" void kernel_launch(void* const* d_in, const int* in_sizes, int n_in,
                              void* d_out, int out_size) {
    const float* inputs  = (const float*)d_in[0];
    const float* state   = (const float*)d_in[1];
    const float* kernels = (const float*)d_in[2];
    const float* biases  = (const float*)d_in[3];
    const float* projs   = (const float*)d_in[4];
    const float* gamma   = (const float*)d_in[5];
    const float* beta    = (const float*)d_in[6];
    const float* convw   = (const float*)d_in[7];
    const float* convb   = (const float*)d_in[8];
    float* out = (float*)d_out;

    cudaFuncSetAttribute(k_scan, cudaFuncAttributeMaxDynamicSharedMemorySize,
                         SM_BYTES);
    cudaFuncSetAttribute(k_gemm_tc, cudaFuncAttributeMaxDynamicSharedMemorySize,
                         SMEM_TC);

    float* BUF = nullptr;
    float* XG  = nullptr;
    __nv_bfloat16 *Ah, *Am, *Whp, *Wmp;
    cudaGetSymbolAddress((void**)&BUF, g_BUF);
    cudaGetSymbolAddress((void**)&XG, g_XG);
    cudaGetSymbolAddress((void**)&Ah, g_Ah);
    cudaGetSymbolAddress((void**)&Am, g_Am);
    cudaGetSymbolAddress((void**)&Whp, g_Wh);
    cudaGetSymbolAddress((void**)&Wmp, g_Wm);
    const size_t BUFSZ = (size_t)Bb * Tt * Pdim;
    float* A  = BUF;
    float* Bu = BUF + BUFSZ;
    float* Cu = BUF + 2 * BUFSZ;

    k_init<<<(Bb * Ddim + 255) / 256, 256>>>(state);

    const float* cur = inputs;
    for (int l = 0; l < 4; l++) {
        int T = (l < 2) ? 512 : 511;
        int Mrows = Bb * T;
        const float* Wx = kernels + (size_t)l * 2 * Pdim * G4;
        const float* Wh = Wx + (size_t)Pdim * G4;
        const float* bi = biases + l * G4;
        const float* Pw = projs + (size_t)l * Ddim * Pdim;

        // convert activations + weights to bf16 (h, m) splits
        int na4 = Mrows * Pdim / 4;
        k_cvt<<<(na4 + 255) / 256, 256>>>(cur, Ah, Am, na4);
        int nw4 = Pdim * G4 / 4;
        k_cvt<<<(nw4 + 255) / 256, 256>>>(Wx, Whp, Wmp, nw4);

        // pre-activations XG = cur @ Wx + bias (tensor cores)
        dim3 gx(G4 / 128, (Mrows + 127) / 128);
        k_gemm_tc<<<gx, 256, SMEM_TC>>>(Ah, Am, Whp, Wmp, bi, XG,
                                        Mrows, G4, Pdim, 0);

        // whole-layer recurrence in ONE persistent launch
        k_rst<<<1, 1>>>();
        k_scan<<<NCTA, NTHR, SM_BYTES>>>(Wh, Pw, XG, A, T);

        // layernorm
        float* LNout;
        if (l == 0)      LNout = Bu;
        else if (l == 1) LNout = Cu;
        else if (l == 2) LNout = Cu;
        else             LNout = out;
        k_ln<<<Mrows, 256>>>(A, LNout, gamma, beta);

        if (l == 1) {
            // temporal conv (window 2, VALID) on tensor cores
            int nc4 = Bb * Tt * Pdim / 4;
            k_cvt<<<(nc4 + 255) / 256, 256>>>(Cu, Ah, Am, nc4);
            int ncw4 = 2 * Pdim * Pdim / 4;
            k_cvt<<<(ncw4 + 255) / 256, 256>>>(convw, Whp, Wmp, ncw4);
            int Mc = Bb * 511;
            dim3 gc(Pdim / 128, (Mc + 127) / 128);
            k_gemm_tc<<<gc, 256, SMEM_TC>>>(Ah, Am, Whp, Wmp, convb, Bu,
                                            Mc, Pdim, 2 * Pdim, 1);
            cur = Bu;
        } else if (l == 0) {
            cur = Bu;
        } else if (l == 2) {
            cur = Cu;
        }
    }

    // outputs: out [16,511,1024], then c [16,2048], then h [16,1024]
    size_t off_c = (size_t)Bb * 511 * Pdim;
    size_t off_h = off_c + (size_t)Bb * Ddim;
    k_out_ch<<<(Bb * Ddim + 255) / 256, 256>>>(out + off_c, out + off_h);
}

// round 15
// speedup vs baseline: 1.1763x; 1.0574x over previous
#include <cuda_runtime.h>
#include <cuda_bf16.h>
#include <math.h>

#define Bb   16
#define Tt   512
#define Pdim 1024
#define Ddim 2048
#define G4   8192      // 4*D
#define LNEPS 1e-3f

#define NCTA 128       // persistent-scan grid (all co-resident; <= 148 SMs)
#define NTHR 256

// smem layout (float offsets) for scan kernel
#define SM_HST    0        // H transposed [1024][20] (pad) = 20480 floats (80KB)
#define SM_WT     20480    // weight tile ring [3][64][64] = 12288 floats (48KB)
#define SM_GRED   32768    // phase A partials [8][16][64] = 8192 floats (32KB)
#define SM_HPART  32768    // phase B partials (union w/ Gred)
#define SM_PWS    40960    // persistent Pw slice [2048][8] = 16384 floats (64KB)
#define SM_FLOATS 57344
#define SM_BYTES  (SM_FLOATS * 4)   // 229376 B

// tensor-GEMM smem (bytes per buffer)
#define SA_H 0          // A hi: [128][40 bf16] = 10240 B (80 B rows, ldmatrix-safe)
#define SA_M 10240      // A lo
#define SB_H 20480      // B hi: [32][136 bf16] = 8704 B (272 B rows)
#define SB_M 29184      // B lo
#define BUFB 37888
#define SMEM_TC (2 * BUFB)   // 75776 B

// ---------------- scratch (static device globals; no allocation) -------------
__device__ float g_XG[(size_t)Bb * Tt * G4];        // 256 MB: pre-activations
__device__ float g_BUF[3][(size_t)Bb * Tt * Pdim];  // 3 x 32 MB ping-pong
__device__ float g_ST[Ddim * Bb];                   // s transposed [d][b]
__device__ float g_HT[Pdim * Bb];                   // h transposed [p][b]
__device__ float g_C[Bb * Ddim];                    // cell state

// bf16 split buffers for tensor GEMM
__device__ __nv_bfloat16 g_Ah[(size_t)Bb * Tt * Pdim];
__device__ __nv_bfloat16 g_Am[(size_t)Bb * Tt * Pdim];
__device__ __nv_bfloat16 g_Wh[(size_t)Pdim * G4];   // covers conv W (2048x1024) too
__device__ __nv_bfloat16 g_Wm[(size_t)Pdim * G4];

// grid barrier: monotonic counter
__device__ unsigned g_cnt;

__device__ __forceinline__ float sigm(float x) { return 1.0f / (1.0f + expf(-x)); }

// ---------------- packed f32x2 helpers ---------------------------------------
__device__ __forceinline__ unsigned long long fma2(unsigned long long a,
                                                   unsigned long long b,
                                                   unsigned long long c) {
    unsigned long long d;
    asm("fma.rn.f32x2 %0, %1, %2, %3;" : "=l"(d) : "l"(a), "l"(b), "l"(c));
    return d;
}
__device__ __forceinline__ unsigned long long pack2(float lo, float hi) {
    unsigned long long r;
    asm("mov.b64 %0, {%1, %2};" : "=l"(r) : "f"(lo), "f"(hi));
    return r;
}
__device__ __forceinline__ float2 unpack2(unsigned long long v) {
    float2 r;
    asm("mov.b64 {%0, %1}, %2;" : "=f"(r.x), "=f"(r.y) : "l"(v));
    return r;
}

// ---------------- mma / ldmatrix / cp.async helpers --------------------------
__device__ __forceinline__ void ldsm_x4(unsigned* r, unsigned addr) {
    asm volatile("ldmatrix.sync.aligned.m8n8.x4.shared.b16 {%0,%1,%2,%3}, [%4];"
                 : "=r"(r[0]), "=r"(r[1]), "=r"(r[2]), "=r"(r[3]) : "r"(addr));
}
__device__ __forceinline__ void ldsm_x2t(unsigned* r, unsigned addr) {
    asm volatile("ldmatrix.sync.aligned.m8n8.x2.trans.shared.b16 {%0,%1}, [%2];"
                 : "=r"(r[0]), "=r"(r[1]) : "r"(addr));
}
__device__ __forceinline__ void mma_bf16(float* c, const unsigned* a, const unsigned* b) {
    asm volatile("mma.sync.aligned.m16n8k16.row.col.f32.bf16.bf16.f32 "
                 "{%0,%1,%2,%3}, {%4,%5,%6,%7}, {%8,%9}, {%0,%1,%2,%3};"
                 : "+f"(c[0]), "+f"(c[1]), "+f"(c[2]), "+f"(c[3])
                 : "r"(a[0]), "r"(a[1]), "r"(a[2]), "r"(a[3]),
                   "r"(b[0]), "r"(b[1]));
}
__device__ __forceinline__ void cpa16z(unsigned dst, const void* src, int sz) {
    asm volatile("cp.async.cg.shared.global [%0], [%1], 16, %2;"
                 :: "r"(dst), "l"(src), "r"(sz));
}
__device__ __forceinline__ void cpa16(unsigned dst, const void* src) {
    asm volatile("cp.async.cg.shared.global [%0], [%1], 16;"
                 :: "r"(dst), "l"(src));
}
__device__ __forceinline__ void cpa_commit() {
    asm volatile("cp.async.commit_group;" ::: "memory");
}
__device__ __forceinline__ void cpa_wait1() {
    asm volatile("cp.async.wait_group 1;" ::: "memory");
}
__device__ __forceinline__ void cpa_wait0() {
    asm volatile("cp.async.wait_group 0;" ::: "memory");
}

// ---------------- software grid barrier (monotonic, red.release) ------------
__device__ __forceinline__ void grid_sync(unsigned& target) {
    __syncthreads();
    target += NCTA;
    if (threadIdx.x == 0) {
        __threadfence();
        asm volatile("red.release.gpu.global.add.u32 [%0], 1;" :: "l"(&g_cnt));
        unsigned v;
        do {
            asm volatile("ld.acquire.gpu.global.u32 %0, [%1];" : "=r"(v) : "l"(&g_cnt));
        } while (v < target);
    }
    __syncthreads();
}

// ---------------- init / reset ----------------------------------------------
__global__ void k_init(const float* __restrict__ state) {
    int i = blockIdx.x * blockDim.x + threadIdx.x;
    if (i < Bb * Ddim) g_C[i] = state[i];
    if (i < Bb * Pdim) {
        int b = i / Pdim, p = i % Pdim;
        g_HT[p * Bb + b] = state[Bb * Ddim + b * Ddim + p];
    }
}
__global__ void k_rst() { g_cnt = 0; }

// ---------------- fp32 -> bf16 (hi, lo) split conversion ---------------------
__global__ void k_cvt(const float* __restrict__ src, __nv_bfloat16* __restrict__ h,
                      __nv_bfloat16* __restrict__ m, int n4) {
    int i = blockIdx.x * blockDim.x + threadIdx.x;
    if (i < n4) {
        float4 v = ((const float4*)src)[i];
        float vv[4] = {v.x, v.y, v.z, v.w};
        __nv_bfloat16 hv[4], mv[4];
#pragma unroll
        for (int j = 0; j < 4; j++) {
            hv[j] = __float2bfloat16_rn(vv[j]);
            mv[j] = __float2bfloat16_rn(vv[j] - __bfloat162float(hv[j]));
        }
        *(uint2*)&h[(size_t)i * 4] = *(uint2*)hv;
        *(uint2*)&m[(size_t)i * 4] = *(uint2*)mv;
    }
}

// ---------------- tensor-core split GEMM: C = A @ W + bias -------------------
__global__ void __launch_bounds__(256) k_gemm_tc(
    const __nv_bfloat16* __restrict__ Ah, const __nv_bfloat16* __restrict__ Am,
    const __nv_bfloat16* __restrict__ Wh, const __nv_bfloat16* __restrict__ Wm,
    const float* __restrict__ bias, float* __restrict__ C,
    int M, int N, int K, int convmode)
{
    extern __shared__ char gsm[];
    const unsigned sbase0 = (unsigned)__cvta_generic_to_shared(gsm);

    const int tid = threadIdx.x;
    const int l = tid & 31;
    const int wid = tid >> 5;
    const int wm = wid >> 2, wn = wid & 3;    // 2 x 4 warp grid
    const int m0 = blockIdx.y * 128, n0 = blockIdx.x * 128;
    const int nk = K / 32;

    float c[4][4][4];
#pragma unroll
    for (int a = 0; a < 4; a++)
#pragma unroll
        for (int b = 0; b < 4; b++)
#pragma unroll
            for (int d = 0; d < 4; d++) c[a][b][d] = 0.0f;

    auto stage = [&](int kt, int buf) {
        const unsigned sb = sbase0 + (unsigned)(buf * BUFB);
        const int k0 = kt * 32;
#pragma unroll
        for (int i = 0; i < 2; i++) {
            int u = tid * 2 + i;
            int ar = u >> 2, au = u & 3;
            int r = m0 + ar;
            int ok = (r < M) ? 16 : 0;
            size_t abase = 0;
            if (ok) abase = convmode ? ((size_t)((r / 511) * 512 + (r % 511))) * 1024
                                     : (size_t)r * (size_t)K;
            unsigned da = sb + SA_H + (unsigned)(ar * 80 + au * 16);
            cpa16z(da, Ah + abase + k0 + au * 8, ok);
            cpa16z(da + (SA_M - SA_H), Am + abase + k0 + au * 8, ok);
            int br = u >> 4, bu = u & 15;
            unsigned db = sb + SB_H + (unsigned)(br * 272 + bu * 16);
            const size_t wof = (size_t)(k0 + br) * (size_t)N + n0 + bu * 8;
            cpa16(db, Wh + wof);
            cpa16(db + (SB_M - SB_H), Wm + wof);
        }
    };

    stage(0, 0);
    cpa_commit();

    const int arow = (l & 7) + ((l & 8) ? 8 : 0);
    const int aoff_hi = (l & 16) ? 16 : 0;
    const int brow_base = (l & 7) + ((l & 8) ? 8 : 0);

    for (int kt = 0; kt < nk; kt++) {
        if (kt + 1 < nk) {
            stage(kt + 1, (kt + 1) & 1);
            cpa_commit();
            cpa_wait1();
        } else {
            cpa_wait0();
        }
        __syncthreads();

        const unsigned sb = sbase0 + (unsigned)((kt & 1) * BUFB);
#pragma unroll
        for (int ks = 0; ks < 2; ks++) {
            unsigned bh[4][2], bm[4][2];
            int brow = ks * 16 + brow_base;
#pragma unroll
            for (int nt = 0; nt < 4; nt++) {
                unsigned ab = sb + SB_H + (unsigned)(brow * 272 + (wn * 32 + nt * 8) * 2);
                ldsm_x2t(bh[nt], ab);
                ldsm_x2t(bm[nt], ab + (SB_M - SB_H));
            }
#pragma unroll
            for (int mt = 0; mt < 4; mt++) {
                unsigned ah4[4], am4[4];
                unsigned aa = sb + SA_H +
                    (unsigned)((wm * 64 + mt * 16 + arow) * 80 + ks * 32 + aoff_hi);
                ldsm_x4(ah4, aa);
                ldsm_x4(am4, aa + (SA_M - SA_H));
#pragma unroll
                for (int nt = 0; nt < 4; nt++) {
                    mma_bf16(c[mt][nt], ah4, bh[nt]);
                    mma_bf16(c[mt][nt], ah4, bm[nt]);
                    mma_bf16(c[mt][nt], am4, bh[nt]);
                }
            }
        }
        __syncthreads();
    }

#pragma unroll
    for (int mt = 0; mt < 4; mt++) {
        int r0 = m0 + wm * 64 + mt * 16 + (l >> 2);
#pragma unroll
        for (int nt = 0; nt < 4; nt++) {
            int col = n0 + wn * 32 + nt * 8 + (l & 3) * 2;
            float b0 = bias[col], b1 = bias[col + 1];
            if (r0 < M)
                *(float2*)&C[(size_t)r0 * N + col] =
                    make_float2(c[mt][nt][0] + b0, c[mt][nt][1] + b1);
            if (r0 + 8 < M)
                *(float2*)&C[(size_t)(r0 + 8) * N + col] =
                    make_float2(c[mt][nt][2] + b0, c[mt][nt][3] + b1);
        }
    }
}

// ---------------- persistent scan: whole-layer LSTM recurrence ---------------
// 128 CTAs x 256 thr. CTA owns gate d-slice [cta*16, cta*16+16) (64 G-cols)
// and proj col-slice [cta*8, cta*8+8). Weights streamed via cp.async in
// 64k x 64col (16KB) tiles, ring of 3, prefetch distance 2 -> latency hidden.
__global__ void __launch_bounds__(NTHR, 1) k_scan(const float* __restrict__ Wh,
                                                  const float* __restrict__ Pw,
                                                  const float* __restrict__ XG,
                                                  float* __restrict__ RAW,
                                                  int T) {
    extern __shared__ float sm[];
    float* Hst   = sm + SM_HST;    // [k][20]
    float* Wt    = sm + SM_WT;     // [3][64][64]
    float* Gred  = sm + SM_GRED;   // [8][16][64]
    float* Hpart = sm + SM_HPART;
    float* Pws   = sm + SM_PWS;    // [2048][8]

    unsigned smem_u32;
    {
        void* p = sm;
        smem_u32 = (unsigned)__cvta_generic_to_shared(p);
    }
    const unsigned wt_u32 = smem_u32 + SM_WT * 4;

    const int tid = threadIdx.x;
    const int cta = blockIdx.x;
    const int d0 = cta * 16;   // gate d-slice
    const int p0 = cta * 8;    // proj col-slice

    const int w    = tid >> 5;
    const int lane = tid & 31;
    const int ksub = lane >> 4;
    const int cq   = lane & 15;
    const int lc   = (cq >> 2) * 16 + (cq & 3) * 4;   // local col (0..63)

    const int gb = tid >> 4;
    const int dl = tid & 15;
    float c_reg = g_C[gb * Ddim + d0 + dl];

    const int b2 = tid & 15;
    const int ks = tid >> 4;          // 16 k-splits of 128

    unsigned bar_target = 0;

    // weight tile fill: 64 rows x 64 cols fp32 = 1024 x 16B; 4 units/thread
    auto fillw = [&](int kt, int buf) {
        const int k0 = kt * 64;
#pragma unroll
        for (int i = 0; i < 4; i++) {
            int u = tid + i * 256;
            int row = u >> 4, q = u & 15;
            unsigned dst = wt_u32 + (unsigned)((buf * 4096 + row * 64 + q * 4) * 4);
            const float* src = Wh + (size_t)(k0 + row) * G4
                             + (q >> 2) * Ddim + d0 + (q & 3) * 4;
            cpa16(dst, src);
        }
    };

    // ---- persistent Pw slice ----
    {
        const float* pwb = Pw + p0;
#pragma unroll 4
        for (int e = tid; e < 4096; e += NTHR) {
            int k = e >> 1, hf = (e & 1) * 4;
            *(float4*)&Pws[k * 8 + hf] =
                *(const float4*)(pwb + (size_t)k * Pdim + hf);
        }
    }
    __syncthreads();

    for (int t = 0; t < T; t++) {
        // ---- issue weight tiles 0,1 ----
        fillw(0, 0); cpa_commit();
        fillw(1, 1); cpa_commit();

        // ---- prefetch XG gates for this step ----
        float xgv[4];
        {
            const float* xgp = XG + ((size_t)gb * T + t) * (size_t)G4 + d0 + dl;
#pragma unroll
            for (int g = 0; g < 4; g++) xgv[g] = xgp[(size_t)g * Ddim];
        }

        // ---- stage H (transposed) into smem (overlaps weight tile fills) ----
#pragma unroll 4
        for (int i = 0; i < 16; i++) {
            int idx = tid + i * NTHR;
            int p = idx >> 2, q4 = (idx & 3) * 4;
            float4 v = *(const float4*)(g_HT + p * Bb + q4);
            *(float4*)&Hst[p * 20 + q4] = v;
        }
        // no explicit sync: tile-0's post-wait sync orders Hst for all warps

        unsigned long long acc[16][2];
#pragma unroll
        for (int b = 0; b < 16; b++) { acc[b][0] = 0ull; acc[b][1] = 0ull; }

        for (int kt = 0; kt < 16; kt++) {
            if (kt == 15) cpa_wait0(); else cpa_wait1();
            __syncthreads();
            if (kt + 2 < 16) {
                fillw(kt + 2, (kt + 2) % 3);
                cpa_commit();
            }
            const float* wtb = Wt + (kt % 3) * 4096;
#pragma unroll
            for (int tt = 0; tt < 4; tt++) {
                int kk = w * 8 + ksub * 4 + tt;
                int kg = kt * 64 + kk;
                ulonglong2 wv = *(const ulonglong2*)&wtb[kk * 64 + lc];
                float4 h0 = *(const float4*)&Hst[kg * 20 + 0];
                float4 h1 = *(const float4*)&Hst[kg * 20 + 4];
                float4 h2 = *(const float4*)&Hst[kg * 20 + 8];
                float4 h3 = *(const float4*)&Hst[kg * 20 + 12];
                float hh[16] = {h0.x, h0.y, h0.z, h0.w, h1.x, h1.y, h1.z, h1.w,
                                h2.x, h2.y, h2.z, h2.w, h3.x, h3.y, h3.z, h3.w};
#pragma unroll
                for (int b = 0; b < 16; b++) {
                    unsigned long long ap = pack2(hh[b], hh[b]);
                    acc[b][0] = fma2(ap, wv.x, acc[b][0]);
                    acc[b][1] = fma2(ap, wv.y, acc[b][1]);
                }
            }
        }

#pragma unroll
        for (int b = 0; b < 16; b++) {
            float2 v0 = unpack2(acc[b][0]);
            float2 v1 = unpack2(acc[b][1]);
            v0.x += __shfl_xor_sync(0xFFFFFFFFu, v0.x, 16);
            v0.y += __shfl_xor_sync(0xFFFFFFFFu, v0.y, 16);
            v1.x += __shfl_xor_sync(0xFFFFFFFFu, v1.x, 16);
            v1.y += __shfl_xor_sync(0xFFFFFFFFu, v1.y, 16);
            if (ksub == 0)
                *(float4*)&Gred[w * 1024 + b * 64 + lc] =
                    make_float4(v0.x, v0.y, v1.x, v1.y);
        }
        __syncthreads();

        // ---- gates + cell update ----
        {
            float gv[4];
#pragma unroll
            for (int g = 0; g < 4; g++) {
                float s = 0.0f;
#pragma unroll
                for (int wf = 0; wf < 8; wf++)
                    s += Gred[wf * 1024 + gb * 64 + g * 16 + dl];
                gv[g] = s + xgv[g];
            }
            float cc = sigm(gv[2] + 1.0f) * c_reg + sigm(gv[0]) * tanhf(gv[1]);
            c_reg = cc;
            float sv = sigm(gv[3]) * tanhf(cc);
            g_ST[(size_t)(d0 + dl) * Bb + gb] = sv;
        }

        grid_sync(bar_target);

        // ---- phase B: H = S @ proj for this CTA's 8 output cols ----
        {
            unsigned long long acc2[4] = {0ull, 0ull, 0ull, 0ull};
            const float* sg = g_ST + (size_t)(ks * 128) * Bb + b2;
            const float* pwk = Pws + ks * 128 * 8;
            float sa0 = sg[0], sa1 = sg[16], sa2 = sg[32], sa3 = sg[48];
            float sb0 = sg[64], sb1 = sg[80], sb2 = sg[96], sb3 = sg[112];
#pragma unroll 1
            for (int k = 0; k < 128; k += 4) {
                float n0v, n1v, n2v, n3v;
                bool more = k < 120;
                if (more) {
                    const float* sq = sg + (size_t)(k + 8) * 16;
                    n0v = sq[0]; n1v = sq[16]; n2v = sq[32]; n3v = sq[48];
                }
#pragma unroll
                for (int u = 0; u < 4; u++) {
                    float s = (u == 0) ? sa0 : (u == 1) ? sa1 : (u == 2) ? sa2 : sa3;
                    unsigned long long sp = pack2(s, s);
                    ulonglong2 w0 = *(const ulonglong2*)(pwk + (k + u) * 8);
                    ulonglong2 w1 = *(const ulonglong2*)(pwk + (k + u) * 8 + 4);
                    acc2[0] = fma2(sp, w0.x, acc2[0]);
                    acc2[1] = fma2(sp, w0.y, acc2[1]);
                    acc2[2] = fma2(sp, w1.x, acc2[2]);
                    acc2[3] = fma2(sp, w1.y, acc2[3]);
                }
                sa0 = sb0; sa1 = sb1; sa2 = sb2; sa3 = sb3;
                sb0 = n0v; sb1 = n1v; sb2 = n2v; sb3 = n3v;
            }
            float* hp = Hpart + (ks * 16 + b2) * 8;
#pragma unroll
            for (int jj = 0; jj < 4; jj++) {
                float2 v = unpack2(acc2[jj]);
                hp[jj * 2 + 0] = v.x;
                hp[jj * 2 + 1] = v.y;
            }
        }
        __syncthreads();
        if (tid < 128) {
            int b = tid >> 3, col = tid & 7;
            float h = 0.0f;
#pragma unroll
            for (int k2 = 0; k2 < 16; k2++)
                h += Hpart[(k2 * 16 + b) * 8 + col];
            g_HT[(p0 + col) * Bb + b] = h;
            RAW[((size_t)b * T + t) * (size_t)Pdim + p0 + col] = h;
        }

        grid_sync(bar_target);
    }

    g_C[gb * Ddim + d0 + dl] = c_reg;
}

// ---------------- layernorm over last dim (1024) ----------------------------
__global__ void k_ln(const float* __restrict__ X, float* __restrict__ Y,
                     const float* __restrict__ gamma, const float* __restrict__ beta) {
    __shared__ float red[256];
    int row = blockIdx.x;
    const float* x = X + (size_t)row * Pdim;
    float* y = Y + (size_t)row * Pdim;
    int tid = threadIdx.x;

    float s = 0.0f;
    for (int i = tid; i < Pdim; i += 256) s += x[i];
    red[tid] = s; __syncthreads();
    for (int o = 128; o > 0; o >>= 1) {
        if (tid < o) red[tid] += red[tid + o];
        __syncthreads();
    }
    float mean = red[0] * (1.0f / Pdim);
    __syncthreads();

    float v = 0.0f;
    for (int i = tid; i < Pdim; i += 256) { float d = x[i] - mean; v += d * d; }
    red[tid] = v; __syncthreads();
    for (int o = 128; o > 0; o >>= 1) {
        if (tid < o) red[tid] += red[tid + o];
        __syncthreads();
    }
    float rstd = rsqrtf(red[0] * (1.0f / Pdim) + LNEPS);
    __syncthreads();

    for (int i = tid; i < Pdim; i += 256)
        y[i] = (x[i] - mean) * rstd * gamma[i] + beta[i];
}

// ---------------- final c,h copy --------------------------------------------
__global__ void k_out_ch(float* __restrict__ oc, float* __restrict__ oh) {
    int idx = blockIdx.x * blockDim.x + threadIdx.x;
    if (idx < Bb * Ddim) oc[idx] = g_C[idx];
    if (idx < Bb * Pdim) {
        int b = idx / Pdim, p = idx % Pdim;
        oh[idx] = g_HT[p * Bb + b];
    }
}

// ---------------- host driver -----------------------------------------------
extern "C" void kernel_launch(void* const* d_in, const int* in_sizes, int n_in,
                              void* d_out, int out_size) {
    const float* inputs  = (const float*)d_in[0];
    const float* state   = (const float*)d_in[1];
    const float* kernels = (const float*)d_in[2];
    const float* biases  = (const float*)d_in[3];
    const float* projs   = (const float*)d_in[4];
    const float* gamma   = (const float*)d_in[5];
    const float* beta    = (const float*)d_in[6];
    const float* convw   = (const float*)d_in[7];
    const float* convb   = (const float*)d_in[8];
    float* out = (float*)d_out;

    cudaFuncSetAttribute(k_scan, cudaFuncAttributeMaxDynamicSharedMemorySize,
                         SM_BYTES);
    cudaFuncSetAttribute(k_gemm_tc, cudaFuncAttributeMaxDynamicSharedMemorySize,
                         SMEM_TC);

    float* BUF = nullptr;
    float* XG  = nullptr;
    __nv_bfloat16 *Ah, *Am, *Whp, *Wmp;
    cudaGetSymbolAddress((void**)&BUF, g_BUF);
    cudaGetSymbolAddress((void**)&XG, g_XG);
    cudaGetSymbolAddress((void**)&Ah, g_Ah);
    cudaGetSymbolAddress((void**)&Am, g_Am);
    cudaGetSymbolAddress((void**)&Whp, g_Wh);
    cudaGetSymbolAddress((void**)&Wmp, g_Wm);
    const size_t BUFSZ = (size_t)Bb * Tt * Pdim;
    float* A  = BUF;
    float* Bu = BUF + BUFSZ;
    float* Cu = BUF + 2 * BUFSZ;

    k_init<<<(Bb * Ddim + 255) / 256, 256>>>(state);

    const float* cur = inputs;
    for (int l = 0; l < 4; l++) {
        int T = (l < 2) ? 512 : 511;
        int Mrows = Bb * T;
        const float* Wx = kernels + (size_t)l * 2 * Pdim * G4;
        const float* Wh = Wx + (size_t)Pdim * G4;
        const float* bi = biases + l * G4;
        const float* Pw = projs + (size_t)l * Ddim * Pdim;

        // convert activations + weights to bf16 (h, m) splits
        int na4 = Mrows * Pdim / 4;
        k_cvt<<<(na4 + 255) / 256, 256>>>(cur, Ah, Am, na4);
        int nw4 = Pdim * G4 / 4;
        k_cvt<<<(nw4 + 255) / 256, 256>>>(Wx, Whp, Wmp, nw4);

        // pre-activations XG = cur @ Wx + bias (tensor cores)
        dim3 gx(G4 / 128, (Mrows + 127) / 128);
        k_gemm_tc<<<gx, 256, SMEM_TC>>>(Ah, Am, Whp, Wmp, bi, XG,
                                        Mrows, G4, Pdim, 0);

        // whole-layer recurrence in ONE persistent launch
        k_rst<<<1, 1>>>();
        k_scan<<<NCTA, NTHR, SM_BYTES>>>(Wh, Pw, XG, A, T);

        // layernorm
        float* LNout;
        if (l == 0)      LNout = Bu;
        else if (l == 1) LNout = Cu;
        else if (l == 2) LNout = Cu;
        else             LNout = out;
        k_ln<<<Mrows, 256>>>(A, LNout, gamma, beta);

        if (l == 1) {
            // temporal conv (window 2, VALID) on tensor cores
            int nc4 = Bb * Tt * Pdim / 4;
            k_cvt<<<(nc4 + 255) / 256, 256>>>(Cu, Ah, Am, nc4);
            int ncw4 = 2 * Pdim * Pdim / 4;
            k_cvt<<<(ncw4 + 255) / 256, 256>>>(convw, Whp, Wmp, ncw4);
            int Mc = Bb * 511;
            dim3 gc(Pdim / 128, (Mc + 127) / 128);
            k_gemm_tc<<<gc, 256, SMEM_TC>>>(Ah, Am, Whp, Wmp, convb, Bu,
                                            Mc, Pdim, 2 * Pdim, 1);
            cur = Bu;
        } else if (l == 0) {
            cur = Bu;
        } else if (l == 2) {
            cur = Cu;
        }
    }

    // outputs: out [16,511,1024], then c [16,2048], then h [16,1024]
    size_t off_c = (size_t)Bb * 511 * Pdim;
    size_t off_h = off_c + (size_t)Bb * Ddim;
    k_out_ch<<<(Bb * Ddim + 255) / 256, 256>>>(out + off_c, out + off_h);
}

// round 16
// speedup vs baseline: 1.2260x; 1.0422x over previous
#include <cuda_runtime.h>
#include <cuda_bf16.h>
#include <math.h>

#define Bb   16
#define Tt   512
#define Pdim 1024
#define Ddim 2048
#define G4   8192      // 4*D
#define LNEPS 1e-3f

#define NCTA 128       // persistent-scan grid (all co-resident; <= 148 SMs)
#define NTHR 256

// scan smem layout (float offsets)
#define SM_SST    0        // s staged [2048][16] = 32768 floats (128KB)
#define SM_WT     32768    // weight tile ring [3][64][64] = 12288 floats (48KB)
#define SM_GRED   45056    // partials [8][16][64] = 8192 floats (32KB)
#define SM_FLOATS 53248
#define SM_BYTES  (SM_FLOATS * 4)   // 212992 B

// k_xg0 smem: Hs [1024][16] + Gred [8][16][64]
#define XG0_SMEM  ((16384 + 8192) * 4)

// tensor-GEMM smem (bytes per buffer)
#define SA_H 0
#define SA_M 10240
#define SB_H 20480
#define SB_M 29184
#define BUFB 37888
#define SMEM_TC (2 * BUFB)

// ---------------- scratch (static device globals; no allocation) -------------
__device__ float g_XG[(size_t)Bb * Tt * G4];        // 256 MB: pre-activations
__device__ float g_BUF[3][(size_t)Bb * Tt * Pdim];  // 3 x 32 MB ping-pong
__device__ float g_PW[(size_t)Ddim * G4];           // 64 MB: P @ Wh per layer
__device__ float g_ST[Ddim * Bb];                   // s transposed [d][b]
__device__ float g_HT[Pdim * Bb];                   // carried h, transposed [p][b]
__device__ float g_C[Bb * Ddim];                    // cell state
__device__ float g_zbias[G4];                       // zero bias (zero-init)

// bf16 split buffers
__device__ __nv_bfloat16 g_Ah[(size_t)Bb * Tt * Pdim];
__device__ __nv_bfloat16 g_Am[(size_t)Bb * Tt * Pdim];
__device__ __nv_bfloat16 g_Wh2[(size_t)Pdim * G4];
__device__ __nv_bfloat16 g_Wm2[(size_t)Pdim * G4];
__device__ __nv_bfloat16 g_SA[(size_t)Bb * Tt * Ddim];   // s hi (rows b*T+t)
__device__ __nv_bfloat16 g_SM[(size_t)Bb * Tt * Ddim];   // s lo

// grid barrier: monotonic counter
__device__ unsigned g_cnt;

__device__ __forceinline__ float sigm(float x) { return 1.0f / (1.0f + expf(-x)); }

// ---------------- packed f32x2 helpers ---------------------------------------
__device__ __forceinline__ unsigned long long fma2(unsigned long long a,
                                                   unsigned long long b,
                                                   unsigned long long c) {
    unsigned long long d;
    asm("fma.rn.f32x2 %0, %1, %2, %3;" : "=l"(d) : "l"(a), "l"(b), "l"(c));
    return d;
}
__device__ __forceinline__ unsigned long long pack2(float lo, float hi) {
    unsigned long long r;
    asm("mov.b64 %0, {%1, %2};" : "=l"(r) : "f"(lo), "f"(hi));
    return r;
}
__device__ __forceinline__ float2 unpack2(unsigned long long v) {
    float2 r;
    asm("mov.b64 {%0, %1}, %2;" : "=f"(r.x), "=f"(r.y) : "l"(v));
    return r;
}

// ---------------- mma / ldmatrix / cp.async helpers --------------------------
__device__ __forceinline__ void ldsm_x4(unsigned* r, unsigned addr) {
    asm volatile("ldmatrix.sync.aligned.m8n8.x4.shared.b16 {%0,%1,%2,%3}, [%4];"
                 : "=r"(r[0]), "=r"(r[1]), "=r"(r[2]), "=r"(r[3]) : "r"(addr));
}
__device__ __forceinline__ void ldsm_x2t(unsigned* r, unsigned addr) {
    asm volatile("ldmatrix.sync.aligned.m8n8.x2.trans.shared.b16 {%0,%1}, [%2];"
                 : "=r"(r[0]), "=r"(r[1]) : "r"(addr));
}
__device__ __forceinline__ void mma_bf16(float* c, const unsigned* a, const unsigned* b) {
    asm volatile("mma.sync.aligned.m16n8k16.row.col.f32.bf16.bf16.f32 "
                 "{%0,%1,%2,%3}, {%4,%5,%6,%7}, {%8,%9}, {%0,%1,%2,%3};"
                 : "+f"(c[0]), "+f"(c[1]), "+f"(c[2]), "+f"(c[3])
                 : "r"(a[0]), "r"(a[1]), "r"(a[2]), "r"(a[3]),
                   "r"(b[0]), "r"(b[1]));
}
__device__ __forceinline__ void cpa16z(unsigned dst, const void* src, int sz) {
    asm volatile("cp.async.cg.shared.global [%0], [%1], 16, %2;"
                 :: "r"(dst), "l"(src), "r"(sz));
}
__device__ __forceinline__ void cpa16(unsigned dst, const void* src) {
    asm volatile("cp.async.cg.shared.global [%0], [%1], 16;"
                 :: "r"(dst), "l"(src));
}
__device__ __forceinline__ void cpa_commit() {
    asm volatile("cp.async.commit_group;" ::: "memory");
}
__device__ __forceinline__ void cpa_wait1() {
    asm volatile("cp.async.wait_group 1;" ::: "memory");
}
__device__ __forceinline__ void cpa_wait0() {
    asm volatile("cp.async.wait_group 0;" ::: "memory");
}

// ---------------- software grid barrier (monotonic, red.release) ------------
__device__ __forceinline__ void grid_sync(unsigned& target) {
    __syncthreads();
    target += NCTA;
    if (threadIdx.x == 0) {
        __threadfence();
        asm volatile("red.release.gpu.global.add.u32 [%0], 1;" :: "l"(&g_cnt));
        unsigned v;
        do {
            asm volatile("ld.acquire.gpu.global.u32 %0, [%1];" : "=r"(v) : "l"(&g_cnt));
        } while (v < target);
    }
    __syncthreads();
}

// ---------------- init / reset ----------------------------------------------
__global__ void k_init(const float* __restrict__ state) {
    int i = blockIdx.x * blockDim.x + threadIdx.x;
    if (i < Bb * Ddim) g_C[i] = state[i];
    if (i < Bb * Pdim) {
        int b = i / Pdim, p = i % Pdim;
        g_HT[p * Bb + b] = state[Bb * Ddim + b * Ddim + p];
    }
}
__global__ void k_rst() { g_cnt = 0; }

// ---------------- fp32 -> bf16 (hi, lo) split conversion ---------------------
__global__ void k_cvt(const float* __restrict__ src, __nv_bfloat16* __restrict__ h,
                      __nv_bfloat16* __restrict__ m, int n4) {
    int i = blockIdx.x * blockDim.x + threadIdx.x;
    if (i < n4) {
        float4 v = ((const float4*)src)[i];
        float vv[4] = {v.x, v.y, v.z, v.w};
        __nv_bfloat16 hv[4], mv[4];
#pragma unroll
        for (int j = 0; j < 4; j++) {
            hv[j] = __float2bfloat16_rn(vv[j]);
            mv[j] = __float2bfloat16_rn(vv[j] - __bfloat162float(hv[j]));
        }
        *(uint2*)&h[(size_t)i * 4] = *(uint2*)hv;
        *(uint2*)&m[(size_t)i * 4] = *(uint2*)mv;
    }
}

// ---------------- tensor-core split GEMM: C = A @ W + bias -------------------
__global__ void __launch_bounds__(256) k_gemm_tc(
    const __nv_bfloat16* __restrict__ Ah, const __nv_bfloat16* __restrict__ Am,
    const __nv_bfloat16* __restrict__ Wh, const __nv_bfloat16* __restrict__ Wm,
    const float* __restrict__ bias, float* __restrict__ C,
    int M, int N, int K, int convmode)
{
    extern __shared__ char gsm[];
    const unsigned sbase0 = (unsigned)__cvta_generic_to_shared(gsm);

    const int tid = threadIdx.x;
    const int l = tid & 31;
    const int wid = tid >> 5;
    const int wm = wid >> 2, wn = wid & 3;
    const int m0 = blockIdx.y * 128, n0 = blockIdx.x * 128;
    const int nk = K / 32;

    float c[4][4][4];
#pragma unroll
    for (int a = 0; a < 4; a++)
#pragma unroll
        for (int b = 0; b < 4; b++)
#pragma unroll
            for (int d = 0; d < 4; d++) c[a][b][d] = 0.0f;

    auto stage = [&](int kt, int buf) {
        const unsigned sb = sbase0 + (unsigned)(buf * BUFB);
        const int k0 = kt * 32;
#pragma unroll
        for (int i = 0; i < 2; i++) {
            int u = tid * 2 + i;
            int ar = u >> 2, au = u & 3;
            int r = m0 + ar;
            int ok = (r < M) ? 16 : 0;
            size_t abase = 0;
            if (ok) abase = convmode ? ((size_t)((r / 511) * 512 + (r % 511))) * 1024
                                     : (size_t)r * (size_t)K;
            unsigned da = sb + SA_H + (unsigned)(ar * 80 + au * 16);
            cpa16z(da, Ah + abase + k0 + au * 8, ok);
            cpa16z(da + (SA_M - SA_H), Am + abase + k0 + au * 8, ok);
            int br = u >> 4, bu = u & 15;
            unsigned db = sb + SB_H + (unsigned)(br * 272 + bu * 16);
            const size_t wof = (size_t)(k0 + br) * (size_t)N + n0 + bu * 8;
            cpa16(db, Wh + wof);
            cpa16(db + (SB_M - SB_H), Wm + wof);
        }
    };

    stage(0, 0);
    cpa_commit();

    const int arow = (l & 7) + ((l & 8) ? 8 : 0);
    const int aoff_hi = (l & 16) ? 16 : 0;
    const int brow_base = (l & 7) + ((l & 8) ? 8 : 0);

    for (int kt = 0; kt < nk; kt++) {
        if (kt + 1 < nk) {
            stage(kt + 1, (kt + 1) & 1);
            cpa_commit();
            cpa_wait1();
        } else {
            cpa_wait0();
        }
        __syncthreads();

        const unsigned sb = sbase0 + (unsigned)((kt & 1) * BUFB);
#pragma unroll
        for (int ks = 0; ks < 2; ks++) {
            unsigned bh[4][2], bm[4][2];
            int brow = ks * 16 + brow_base;
#pragma unroll
            for (int nt = 0; nt < 4; nt++) {
                unsigned ab = sb + SB_H + (unsigned)(brow * 272 + (wn * 32 + nt * 8) * 2);
                ldsm_x2t(bh[nt], ab);
                ldsm_x2t(bm[nt], ab + (SB_M - SB_H));
            }
#pragma unroll
            for (int mt = 0; mt < 4; mt++) {
                unsigned ah4[4], am4[4];
                unsigned aa = sb + SA_H +
                    (unsigned)((wm * 64 + mt * 16 + arow) * 80 + ks * 32 + aoff_hi);
                ldsm_x4(ah4, aa);
                ldsm_x4(am4, aa + (SA_M - SA_H));
#pragma unroll
                for (int nt = 0; nt < 4; nt++) {
                    mma_bf16(c[mt][nt], ah4, bh[nt]);
                    mma_bf16(c[mt][nt], ah4, bm[nt]);
                    mma_bf16(c[mt][nt], am4, bh[nt]);
                }
            }
        }
        __syncthreads();
    }

#pragma unroll
    for (int mt = 0; mt < 4; mt++) {
        int r0 = m0 + wm * 64 + mt * 16 + (l >> 2);
#pragma unroll
        for (int nt = 0; nt < 4; nt++) {
            int col = n0 + wn * 32 + nt * 8 + (l & 3) * 2;
            float b0 = bias[col], b1 = bias[col + 1];
            if (r0 < M)
                *(float2*)&C[(size_t)r0 * N + col] =
                    make_float2(c[mt][nt][0] + b0, c[mt][nt][1] + b1);
            if (r0 + 8 < M)
                *(float2*)&C[(size_t)(r0 + 8) * N + col] =
                    make_float2(c[mt][nt][2] + b0, c[mt][nt][3] + b1);
        }
    }
}

// ---------------- fold h0 @ Wh into XG[:, 0, :] ------------------------------
// 128 CTAs x 256 thr; CTA owns the same 64 gate-cols as the scan. K = 1024.
__global__ void __launch_bounds__(256) k_xg0(const float* __restrict__ Wh,
                                             float* __restrict__ XG, int T) {
    extern __shared__ float sm[];
    float* Hs   = sm;            // [1024][16]
    float* Gred = sm + 16384;    // [8][16][64]

    const int tid = threadIdx.x;
    const int cta = blockIdx.x;
    const int d0 = cta * 16;

    const int w    = tid >> 5;
    const int lane = tid & 31;
    const int ksub = lane >> 4;
    const int cq   = lane & 15;
    const int lc   = (cq >> 2) * 16 + (cq & 3) * 4;
    const int wcol = (cq >> 2) * Ddim + d0 + (cq & 3) * 4;

    const int gb = tid >> 4;
    const int dl = tid & 15;

    // stage h0 (transposed [p][b]) into smem
#pragma unroll
    for (int i = 0; i < 16; i++) {
        int idx = tid + i * 256;
        ((float4*)Hs)[idx] = ((const float4*)g_HT)[idx];
    }
    __syncthreads();

    unsigned long long acc[16][2];
#pragma unroll
    for (int b = 0; b < 16; b++) { acc[b][0] = 0ull; acc[b][1] = 0ull; }

    for (int kt = 0; kt < 16; kt++) {
#pragma unroll
        for (int tt = 0; tt < 4; tt++) {
            int kg = kt * 64 + w * 8 + ksub * 4 + tt;
            ulonglong2 wv = *(const ulonglong2*)(Wh + (size_t)kg * G4 + wcol);
            float4 h0 = *(const float4*)&Hs[kg * 16 + 0];
            float4 h1 = *(const float4*)&Hs[kg * 16 + 4];
            float4 h2 = *(const float4*)&Hs[kg * 16 + 8];
            float4 h3 = *(const float4*)&Hs[kg * 16 + 12];
            float hh[16] = {h0.x, h0.y, h0.z, h0.w, h1.x, h1.y, h1.z, h1.w,
                            h2.x, h2.y, h2.z, h2.w, h3.x, h3.y, h3.z, h3.w};
#pragma unroll
            for (int b = 0; b < 16; b++) {
                unsigned long long ap = pack2(hh[b], hh[b]);
                acc[b][0] = fma2(ap, wv.x, acc[b][0]);
                acc[b][1] = fma2(ap, wv.y, acc[b][1]);
            }
        }
    }

#pragma unroll
    for (int b = 0; b < 16; b++) {
        float2 v0 = unpack2(acc[b][0]);
        float2 v1 = unpack2(acc[b][1]);
        v0.x += __shfl_xor_sync(0xFFFFFFFFu, v0.x, 16);
        v0.y += __shfl_xor_sync(0xFFFFFFFFu, v0.y, 16);
        v1.x += __shfl_xor_sync(0xFFFFFFFFu, v1.x, 16);
        v1.y += __shfl_xor_sync(0xFFFFFFFFu, v1.y, 16);
        if (ksub == 0)
            *(float4*)&Gred[w * 1024 + b * 64 + lc] =
                make_float4(v0.x, v0.y, v1.x, v1.y);
    }
    __syncthreads();

#pragma unroll
    for (int g = 0; g < 4; g++) {
        float s = 0.0f;
#pragma unroll
        for (int wf = 0; wf < 8; wf++)
            s += Gred[wf * 1024 + gb * 64 + g * 16 + dl];
        float* xp = XG + ((size_t)gb * T) * (size_t)G4 + (size_t)g * Ddim + d0 + dl;
        *xp += s;
    }
}

// ---------------- persistent scan: fused recurrence, ONE barrier/step --------
// G_t = XG_t + s_{t-1} @ PW  (PW = P@Wh, K = 2048). CTA owns 64 gate-cols
// (d-slice of 16 x 4 gates). Gates emit s as fp32 (exchange) + bf16 hi/lo
// (for the offline h GEMM). No phase B, no Pw, no h in the loop.
__global__ void __launch_bounds__(NTHR, 1) k_scan(const float* __restrict__ PW,
                                                  const float* __restrict__ XG,
                                                  int T) {
    extern __shared__ float sm[];
    float* Sst  = sm + SM_SST;   // [2048][16]
    float* Wt   = sm + SM_WT;    // [3][64][64]
    float* Gred = sm + SM_GRED;  // [8][16][64]

    unsigned smem_u32 = (unsigned)__cvta_generic_to_shared((void*)sm);
    const unsigned wt_u32 = smem_u32 + SM_WT * 4;

    const int tid = threadIdx.x;
    const int cta = blockIdx.x;
    const int d0 = cta * 16;

    const int w    = tid >> 5;
    const int lane = tid & 31;
    const int ksub = lane >> 4;
    const int cq   = lane & 15;
    const int lc   = (cq >> 2) * 16 + (cq & 3) * 4;

    const int gb = tid >> 4;
    const int dl = tid & 15;
    float c_reg = g_C[gb * Ddim + d0 + dl];

    unsigned bar_target = 0;

    // weight tile fill: 64 rows x 64 cols fp32 = 1024 x 16B; 4 units/thread
    auto fillw = [&](int kt, int buf) {
        const int k0 = kt * 64;
#pragma unroll
        for (int i = 0; i < 4; i++) {
            int u = tid + i * 256;
            int row = u >> 4, q = u & 15;
            unsigned dst = wt_u32 + (unsigned)((buf * 4096 + row * 64 + q * 4) * 4);
            const float* src = PW + (size_t)(k0 + row) * G4
                             + (q >> 2) * Ddim + d0 + (q & 3) * 4;
            cpa16(dst, src);
        }
    };

    for (int t = 0; t < T; t++) {
        // ---- prefetch XG gates ----
        float xgv[4];
        {
            const float* xgp = XG + ((size_t)gb * T + t) * (size_t)G4 + d0 + dl;
#pragma unroll
            for (int g = 0; g < 4; g++) xgv[g] = xgp[(size_t)g * Ddim];
        }

        float gsum[4] = {0.f, 0.f, 0.f, 0.f};

        if (t > 0) {
            // issue weight tiles 0,1
            fillw(0, 0); cpa_commit();
            fillw(1, 1); cpa_commit();

            // stage s_{t-1} (transposed [k][16]) into smem
#pragma unroll 4
            for (int i = 0; i < 32; i++) {
                int idx = tid + i * NTHR;
                ((float4*)Sst)[idx] = ((const float4*)g_ST)[idx];
            }

            unsigned long long acc[16][2];
#pragma unroll
            for (int b = 0; b < 16; b++) { acc[b][0] = 0ull; acc[b][1] = 0ull; }

            for (int kt = 0; kt < 32; kt++) {
                if (kt == 31) cpa_wait0(); else cpa_wait1();
                __syncthreads();
                if (kt + 2 < 32) {
                    fillw(kt + 2, (kt + 2) % 3);
                    cpa_commit();
                }
                const float* wtb = Wt + (kt % 3) * 4096;
#pragma unroll
                for (int tt = 0; tt < 4; tt++) {
                    int kk = w * 8 + ksub * 4 + tt;
                    int kg = kt * 64 + kk;
                    ulonglong2 wv = *(const ulonglong2*)&wtb[kk * 64 + lc];
                    float4 s0 = *(const float4*)&Sst[kg * 16 + 0];
                    float4 s1 = *(const float4*)&Sst[kg * 16 + 4];
                    float4 s2 = *(const float4*)&Sst[kg * 16 + 8];
                    float4 s3 = *(const float4*)&Sst[kg * 16 + 12];
                    float hh[16] = {s0.x, s0.y, s0.z, s0.w, s1.x, s1.y, s1.z, s1.w,
                                    s2.x, s2.y, s2.z, s2.w, s3.x, s3.y, s3.z, s3.w};
#pragma unroll
                    for (int b = 0; b < 16; b++) {
                        unsigned long long ap = pack2(hh[b], hh[b]);
                        acc[b][0] = fma2(ap, wv.x, acc[b][0]);
                        acc[b][1] = fma2(ap, wv.y, acc[b][1]);
                    }
                }
            }

#pragma unroll
            for (int b = 0; b < 16; b++) {
                float2 v0 = unpack2(acc[b][0]);
                float2 v1 = unpack2(acc[b][1]);
                v0.x += __shfl_xor_sync(0xFFFFFFFFu, v0.x, 16);
                v0.y += __shfl_xor_sync(0xFFFFFFFFu, v0.y, 16);
                v1.x += __shfl_xor_sync(0xFFFFFFFFu, v1.x, 16);
                v1.y += __shfl_xor_sync(0xFFFFFFFFu, v1.y, 16);
                if (ksub == 0)
                    *(float4*)&Gred[w * 1024 + b * 64 + lc] =
                        make_float4(v0.x, v0.y, v1.x, v1.y);
            }
            __syncthreads();

#pragma unroll
            for (int g = 0; g < 4; g++) {
                float s = 0.0f;
#pragma unroll
                for (int wf = 0; wf < 8; wf++)
                    s += Gred[wf * 1024 + gb * 64 + g * 16 + dl];
                gsum[g] = s;
            }
        }

        // ---- gates + cell update + emit s ----
        {
            float gi = gsum[0] + xgv[0];
            float gj = gsum[1] + xgv[1];
            float gf = gsum[2] + xgv[2];
            float go = gsum[3] + xgv[3];
            float cc = sigm(gf + 1.0f) * c_reg + sigm(gi) * tanhf(gj);
            c_reg = cc;
            float sv = sigm(go) * tanhf(cc);
            g_ST[(size_t)(d0 + dl) * Bb + gb] = sv;
            __nv_bfloat16 hi = __float2bfloat16_rn(sv);
            __nv_bfloat16 lo = __float2bfloat16_rn(sv - __bfloat162float(hi));
            size_t row = (size_t)gb * T + t;
            g_SA[row * Ddim + d0 + dl] = hi;
            g_SM[row * Ddim + d0 + dl] = lo;
        }

        grid_sync(bar_target);
    }

    g_C[gb * Ddim + d0 + dl] = c_reg;
}

// ---------------- refresh carried h state from RAW last rows -----------------
__global__ void k_seth(const float* __restrict__ RAW, int T) {
    int idx = blockIdx.x * blockDim.x + threadIdx.x;
    if (idx < Bb * Pdim) {
        int b = idx / Pdim, p = idx % Pdim;
        g_HT[p * Bb + b] = RAW[((size_t)b * T + (T - 1)) * (size_t)Pdim + p];
    }
}

// ---------------- layernorm over last dim (1024) ----------------------------
__global__ void k_ln(const float* __restrict__ X, float* __restrict__ Y,
                     const float* __restrict__ gamma, const float* __restrict__ beta) {
    __shared__ float red[256];
    int row = blockIdx.x;
    const float* x = X + (size_t)row * Pdim;
    float* y = Y + (size_t)row * Pdim;
    int tid = threadIdx.x;

    float s = 0.0f;
    for (int i = tid; i < Pdim; i += 256) s += x[i];
    red[tid] = s; __syncthreads();
    for (int o = 128; o > 0; o >>= 1) {
        if (tid < o) red[tid] += red[tid + o];
        __syncthreads();
    }
    float mean = red[0] * (1.0f / Pdim);
    __syncthreads();

    float v = 0.0f;
    for (int i = tid; i < Pdim; i += 256) { float d = x[i] - mean; v += d * d; }
    red[tid] = v; __syncthreads();
    for (int o = 128; o > 0; o >>= 1) {
        if (tid < o) red[tid] += red[tid + o];
        __syncthreads();
    }
    float rstd = rsqrtf(red[0] * (1.0f / Pdim) + LNEPS);
    __syncthreads();

    for (int i = tid; i < Pdim; i += 256)
        y[i] = (x[i] - mean) * rstd * gamma[i] + beta[i];
}

// ---------------- final c,h copy --------------------------------------------
__global__ void k_out_ch(float* __restrict__ oc, float* __restrict__ oh) {
    int idx = blockIdx.x * blockDim.x + threadIdx.x;
    if (idx < Bb * Ddim) oc[idx] = g_C[idx];
    if (idx < Bb * Pdim) {
        int b = idx / Pdim, p = idx % Pdim;
        oh[idx] = g_HT[p * Bb + b];
    }
}

// ---------------- host driver -----------------------------------------------
extern "C" void kernel_launch(void* const* d_in, const int* in_sizes, int n_in,
                              void* d_out, int out_size) {
    const float* inputs  = (const float*)d_in[0];
    const float* state   = (const float*)d_in[1];
    const float* kernels = (const float*)d_in[2];
    const float* biases  = (const float*)d_in[3];
    const float* projs   = (const float*)d_in[4];
    const float* gamma   = (const float*)d_in[5];
    const float* beta    = (const float*)d_in[6];
    const float* convw   = (const float*)d_in[7];
    const float* convb   = (const float*)d_in[8];
    float* out = (float*)d_out;

    cudaFuncSetAttribute(k_scan, cudaFuncAttributeMaxDynamicSharedMemorySize,
                         SM_BYTES);
    cudaFuncSetAttribute(k_gemm_tc, cudaFuncAttributeMaxDynamicSharedMemorySize,
                         SMEM_TC);
    cudaFuncSetAttribute(k_xg0, cudaFuncAttributeMaxDynamicSharedMemorySize,
                         XG0_SMEM);

    float *BUF, *XG, *PW, *zb;
    __nv_bfloat16 *Ah, *Am, *Whp, *Wmp, *SAh, *SMl;
    cudaGetSymbolAddress((void**)&BUF, g_BUF);
    cudaGetSymbolAddress((void**)&XG, g_XG);
    cudaGetSymbolAddress((void**)&PW, g_PW);
    cudaGetSymbolAddress((void**)&zb, g_zbias);
    cudaGetSymbolAddress((void**)&Ah, g_Ah);
    cudaGetSymbolAddress((void**)&Am, g_Am);
    cudaGetSymbolAddress((void**)&Whp, g_Wh2);
    cudaGetSymbolAddress((void**)&Wmp, g_Wm2);
    cudaGetSymbolAddress((void**)&SAh, g_SA);
    cudaGetSymbolAddress((void**)&SMl, g_SM);
    const size_t BUFSZ = (size_t)Bb * Tt * Pdim;
    float* A  = BUF;
    float* Bu = BUF + BUFSZ;
    float* Cu = BUF + 2 * BUFSZ;

    k_init<<<(Bb * Ddim + 255) / 256, 256>>>(state);

    const float* cur = inputs;
    for (int l = 0; l < 4; l++) {
        int T = (l < 2) ? 512 : 511;
        int Mrows = Bb * T;
        const float* Wx  = kernels + (size_t)l * 2 * Pdim * G4;
        const float* Whf = Wx + (size_t)Pdim * G4;
        const float* bi = biases + l * G4;
        const float* Pw = projs + (size_t)l * Ddim * Pdim;

        // XG = cur @ Wx + bias (tensor cores)
        int na4 = Mrows * Pdim / 4;
        k_cvt<<<(na4 + 255) / 256, 256>>>(cur, Ah, Am, na4);
        int nw4 = Pdim * G4 / 4;
        k_cvt<<<(nw4 + 255) / 256, 256>>>(Wx, Whp, Wmp, nw4);
        dim3 gx(G4 / 128, (Mrows + 127) / 128);
        k_gemm_tc<<<gx, 256, SMEM_TC>>>(Ah, Am, Whp, Wmp, bi, XG,
                                        Mrows, G4, Pdim, 0);

        // PW = P @ Wh (tensor cores)
        k_cvt<<<(nw4 + 255) / 256, 256>>>(Whf, Whp, Wmp, nw4);
        int np4 = Ddim * Pdim / 4;
        k_cvt<<<(np4 + 255) / 256, 256>>>(Pw, Ah, Am, np4);
        dim3 gp(G4 / 128, Ddim / 128);
        k_gemm_tc<<<gp, 256, SMEM_TC>>>(Ah, Am, Whp, Wmp, zb, PW,
                                        Ddim, G4, Pdim, 0);

        // fold h0 @ Wh into XG[:, 0, :]
        k_xg0<<<NCTA, 256, XG0_SMEM>>>(Whf, XG, T);

        // fused recurrence: ONE barrier per step
        k_rst<<<1, 1>>>();
        k_scan<<<NCTA, NTHR, SM_BYTES>>>(PW, XG, T);

        // RAW = S_all @ P (tensor cores); s already stored bf16-split by scan
        k_cvt<<<(np4 + 255) / 256, 256>>>(Pw, Whp, Wmp, np4);
        dim3 gr(Pdim / 128, (Mrows + 127) / 128);
        k_gemm_tc<<<gr, 256, SMEM_TC>>>(SAh, SMl, Whp, Wmp, zb, A,
                                        Mrows, Pdim, Ddim, 0);
        k_seth<<<(Bb * Pdim + 255) / 256, 256>>>(A, T);

        // layernorm
        float* LNout;
        if (l == 0)      LNout = Bu;
        else if (l == 1) LNout = Cu;
        else if (l == 2) LNout = Cu;
        else             LNout = out;
        k_ln<<<Mrows, 256>>>(A, LNout, gamma, beta);

        if (l == 1) {
            // temporal conv (window 2, VALID) on tensor cores
            int nc4 = Bb * Tt * Pdim / 4;
            k_cvt<<<(nc4 + 255) / 256, 256>>>(Cu, Ah, Am, nc4);
            int ncw4 = 2 * Pdim * Pdim / 4;
            k_cvt<<<(ncw4 + 255) / 256, 256>>>(convw, Whp, Wmp, ncw4);
            int Mc = Bb * 511;
            dim3 gc(Pdim / 128, (Mc + 127) / 128);
            k_gemm_tc<<<gc, 256, SMEM_TC>>>(Ah, Am, Whp, Wmp, convb, Bu,
                                            Mc, Pdim, 2 * Pdim, 1);
            cur = Bu;
        } else if (l == 0) {
            cur = Bu;
        } else if (l == 2) {
            cur = Cu;
        }
    }

    // outputs: out [16,511,1024], then c [16,2048], then h [16,1024]
    size_t off_c = (size_t)Bb * 511 * Pdim;
    size_t off_h = off_c + (size_t)Bb * Ddim;
    k_out_ch<<<(Bb * Ddim + 255) / 256, 256>>>(out + off_c, out + off_h);
}